// round 7
// baseline (speedup 1.0000x reference)
#include <cuda_runtime.h>
#include <cuda_fp16.h>
#include <stdint.h>
#include <math.h>

#define B_  1024
#define M_  65536
#define D_  384
#define H_  384
#define K_  5

// ---- main kernel tiling ----
#define CH_   8
#define MCH   (M_/CH_)      // 8192
#define BQ    64
#define BN    256
#define BK    64
#define NT_   (MCH/BN)      // 32
#define NTH   512

// smem byte offsets (k_main)
#define SM_QLO 49152                 // Q hi at 0, 64*768B each
#define SM_B   98304
#define BHALF  32768                 // 256 rows * 128B
#define BSTG   65536                 // hi+lo per stage
#define SM_TOT 229376                // SM_B + 2*BSTG

// ---- epilogue GEMM tiling ----
#define KC  32
#define QTP 68
#define MTP 132
#define GBM 64
#define GBN 128

#define RNS 36                       // k_rnn W smem row stride (floats)
#define RROWS 16                     // k_rnn rows per CTA

// ---------------- ptx macros ----------------
#define CP_ASYNC16(dst, src) \
    asm volatile("cp.async.ca.shared.global [%0], [%1], 16;" :: "r"(dst), "l"(src))
#define CP_COMMIT() asm volatile("cp.async.commit_group;" ::: "memory")
#define CP_WAIT1()  asm volatile("cp.async.wait_group 1;" ::: "memory")
#define CP_WAIT0()  asm volatile("cp.async.wait_group 0;" ::: "memory")
#define LDM4(r0, r1, r2, r3, addr) \
    asm volatile("ldmatrix.sync.aligned.m8n8.x4.shared.b16 {%0,%1,%2,%3}, [%4];" \
                 : "=r"(r0), "=r"(r1), "=r"(r2), "=r"(r3) : "r"(addr))
#define MMA16816(c0, c1, c2, c3, a0, a1, a2, a3, b0, b1) \
    asm volatile("mma.sync.aligned.m16n8k16.row.col.f32.f16.f16.f32 " \
                 "{%0,%1,%2,%3}, {%4,%5,%6,%7}, {%8,%9}, {%0,%1,%2,%3};" \
                 : "+f"(c0), "+f"(c1), "+f"(c2), "+f"(c3) \
                 : "r"(a0), "r"(a1), "r"(a2), "r"(a3), "r"(b0), "r"(b1))

// ---------------- scratch (device globals; no allocation) ----------------
__device__ float  g_center[2];
__device__ float2 g_ra[M_];          // (1/||m||, act)
__device__ float  g_rq[B_];
__device__ float  g_candv[B_ * CH_ * K_];
__device__ int    g_candi[B_ * CH_ * K_];
__device__ int    g_topk[B_ * K_];
__device__ float  g_xproj[B_ * 6 * H_];
__device__ float  g_gate[B_ * H_];
__device__ __half g_mem_hi[M_ * D_];
__device__ __half g_mem_lo[M_ * D_];
__device__ __half g_q_hi[B_ * D_];
__device__ __half g_q_lo[B_ * D_];

// ---------------- kernel 0: fp32 -> fp16 hi/lo split ----------------
__global__ void k_split(const float* __restrict__ q, const float* __restrict__ mem) {
    const int n4m = M_ * D_ / 4;
    const int n4q = B_ * D_ / 4;
    int i = blockIdx.x * blockDim.x + threadIdx.x;
    if (i >= n4m + n4q) return;
    float4 v;
    if (i < n4m) v = ((const float4*)mem)[i];
    else         v = ((const float4*)q)[i - n4m];
    float xs[4];
    xs[0] = v.x; xs[1] = v.y; xs[2] = v.z; xs[3] = v.w;
    uint32_t hw[4], lw[4];
    #pragma unroll
    for (int k = 0; k < 4; k++) {
        __half hb = __float2half_rn(xs[k]);
        float lf = xs[k] - __half2float(hb);
        __half lb = __float2half_rn(lf);
        hw[k] = (uint32_t)__half_as_ushort(hb);
        lw[k] = (uint32_t)__half_as_ushort(lb);
    }
    uint2 hp, lp;
    hp.x = hw[0] | (hw[1] << 16); hp.y = hw[2] | (hw[3] << 16);
    lp.x = lw[0] | (lw[1] << 16); lp.y = lw[2] | (lw[3] << 16);
    if (i < n4m) {
        ((uint2*)g_mem_hi)[i] = hp;
        ((uint2*)g_mem_lo)[i] = lp;
    } else {
        ((uint2*)g_q_hi)[i - n4m] = hp;
        ((uint2*)g_q_lo)[i - n4m] = lp;
    }
}

// ---------------- kernel 1: center of spatial_weights ----------------
__global__ void k_center(const float* __restrict__ sw) {
    __shared__ float s0[128], s1[128];
    int i = threadIdx.x;
    float a = 0.f, b = 0.f;
    for (int j = i; j < H_; j += 128) { a += sw[j * 2]; b += sw[j * 2 + 1]; }
    s0[i] = a; s1[i] = b;
    __syncthreads();
    for (int off = 64; off > 0; off >>= 1) {
        if (i < off) { s0[i] += s0[i + off]; s1[i] += s1[i + off]; }
        __syncthreads();
    }
    if (i == 0) { g_center[0] = s0[0] / (float)H_; g_center[1] = s1[0] / (float)H_; }
}

// ---------------- kernel 2: per-row stats ----------------
__global__ void k_prep(const float* __restrict__ query,
                       const float* __restrict__ mem,
                       const float* __restrict__ coords) {
    int w = (blockIdx.x * blockDim.x + threadIdx.x) >> 5;
    int lane = threadIdx.x & 31;
    if (w < M_) {
        const float* row = mem + (size_t)w * D_;
        float ss = 0.f;
        #pragma unroll
        for (int j = 0; j < D_ / 32; j++) { float v = row[lane + j * 32]; ss += v * v; }
        #pragma unroll
        for (int o = 16; o; o >>= 1) ss += __shfl_xor_sync(0xffffffffu, ss, o);
        if (lane == 0) {
            float dx = coords[2 * w]     - g_center[0];
            float dy = coords[2 * w + 1] - g_center[1];
            float2 ra;
            ra.x = 1.f / sqrtf(ss);
            ra.y = 1.f / (1.f + sqrtf(dx * dx + dy * dy));
            g_ra[w] = ra;
        }
    } else if (w < M_ + B_) {
        int b = w - M_;
        const float* row = query + (size_t)b * D_;
        float ss = 0.f;
        #pragma unroll
        for (int j = 0; j < D_ / 32; j++) { float v = row[lane + j * 32]; ss += v * v; }
        #pragma unroll
        for (int o = 16; o; o >>= 1) ss += __shfl_xor_sync(0xffffffffu, ss, o);
        if (lane == 0) g_rq[b] = 1.f / sqrtf(ss);
    }
}

// ---------------- kernel 3: tensor-core GEMM + register top-5 (512 thr) ----------------
__global__ void __launch_bounds__(NTH, 1) k_main() {
    extern __shared__ char smbuf[];
    uint32_t sbase;
    {
        uint64_t tmp = __cvta_generic_to_shared(smbuf);
        sbase = (uint32_t)tmp;
    }

    int tid = threadIdx.x;
    int lane = tid & 31;
    int wid = tid >> 5;
    int wq = (wid >> 3) * 32;       // 0 or 32
    int wm = (wid & 7) * 32;        // 0..224
    int qb = blockIdx.y * BQ;
    int mg0 = blockIdx.x * MCH;

    // resident Q hi/lo (swizzled: 16B chunk c of row r goes to chunk (c&~7)|((c^r)&7))
    for (int i = tid; i < BQ * 48; i += NTH) {
        int r = i / 48;
        int c = i - r * 48;
        int cs = (c & ~7) | ((c ^ r) & 7);
        *(uint4*)(smbuf + r * 768 + cs * 16) = ((const uint4*)(g_q_hi + (qb + r) * D_))[c];
        *(uint4*)(smbuf + SM_QLO + r * 768 + cs * 16) = ((const uint4*)(g_q_lo + (qb + r) * D_))[c];
    }

    float rq[4];
    #pragma unroll
    for (int l = 0; l < 4; l++)
        rq[l] = g_rq[qb + wq + (l >> 1) * 16 + (l & 1) * 8 + (lane >> 2)];

    float tv[4][K_];
    int   tix[4][K_];
    #pragma unroll
    for (int l = 0; l < 4; l++) {
        #pragma unroll
        for (int s = 0; s < K_; s++) { tv[l][s] = -3.4e38f; tix[l][s] = 0; }
    }

    __syncthreads();

    // initial prefetch: tile 0, stage 0 -> buf 0
    {
        const __half* bh_g = g_mem_hi + (size_t)mg0 * D_;
        const __half* bl_g = g_mem_lo + (size_t)mg0 * D_;
        uint32_t dst = sbase + SM_B;
        #pragma unroll
        for (int l = 0; l < 4; l++) {
            int i = tid + l * NTH;
            int r = i >> 3;
            int seg = i & 7;
            uint32_t doff = (uint32_t)(r * 128 + (((seg ^ r) & 7) << 4));
            size_t goff = (size_t)r * D_ + seg * 8;
            CP_ASYNC16(dst + doff, (const void*)(bh_g + goff));
            CP_ASYNC16(dst + BHALF + doff, (const void*)(bl_g + goff));
        }
        CP_COMMIT();
    }

    for (int t = 0; t < NT_; t++) {
        int mg = mg0 + t * BN;

        float acc[2][4][4];
        #pragma unroll
        for (int a = 0; a < 2; a++) {
            #pragma unroll
            for (int b = 0; b < 4; b++) {
                #pragma unroll
                for (int c = 0; c < 4; c++) acc[a][b][c] = 0.f;
            }
        }

        #pragma unroll
        for (int s = 0; s < 6; s++) {
            bool issue = (s < 5) || (t + 1 < NT_);
            if (issue) {
                int kc, mnext;
                uint32_t dst;
                if (s < 5) { kc = (s + 1) * BK; mnext = mg; dst = sbase + SM_B + (uint32_t)(((s + 1) & 1) * BSTG); }
                else       { kc = 0; mnext = mg + BN; dst = sbase + SM_B; }
                const __half* bh_g = g_mem_hi + (size_t)mnext * D_;
                const __half* bl_g = g_mem_lo + (size_t)mnext * D_;
                #pragma unroll
                for (int l = 0; l < 4; l++) {
                    int i = tid + l * NTH;
                    int r = i >> 3;
                    int seg = i & 7;
                    uint32_t doff = (uint32_t)(r * 128 + (((seg ^ r) & 7) << 4));
                    size_t goff = (size_t)r * D_ + kc + seg * 8;
                    CP_ASYNC16(dst + doff, (const void*)(bh_g + goff));
                    CP_ASYNC16(dst + BHALF + doff, (const void*)(bl_g + goff));
                }
                CP_COMMIT();
                CP_WAIT1();
            } else {
                CP_WAIT0();
            }
            __syncthreads();

            uint32_t bbuf = sbase + SM_B + (uint32_t)((s & 1) * BSTG);
            #pragma unroll
            for (int ks = 0; ks < 4; ks++) {
                int c16 = s * 8 + ks * 2 + (lane >> 4);
                uint32_t ah[2][4], al[2][4];
                #pragma unroll
                for (int mt = 0; mt < 2; mt++) {
                    int qrow = wq + mt * 16 + (lane & 15);
                    int cs = (c16 & ~7) | ((c16 ^ qrow) & 7);
                    uint32_t aoff = (uint32_t)(qrow * 768 + cs * 16);
                    LDM4(ah[mt][0], ah[mt][1], ah[mt][2], ah[mt][3], sbase + aoff);
                    LDM4(al[mt][0], al[mt][1], al[mt][2], al[mt][3], sbase + SM_QLO + aoff);
                }
                uint32_t bhf[4][2], blf[4][2];
                #pragma unroll
                for (int p = 0; p < 2; p++) {
                    int n = wm + p * 16 + ((lane >> 4) << 3) + (lane & 7);
                    int cb = ks * 2 + ((lane >> 3) & 1);
                    uint32_t boff = (uint32_t)(n * 128 + (((cb ^ n) & 7) << 4));
                    uint32_t r0, r1, r2, r3;
                    LDM4(r0, r1, r2, r3, bbuf + boff);
                    bhf[2 * p][0] = r0; bhf[2 * p][1] = r1;
                    bhf[2 * p + 1][0] = r2; bhf[2 * p + 1][1] = r3;
                    LDM4(r0, r1, r2, r3, bbuf + BHALF + boff);
                    blf[2 * p][0] = r0; blf[2 * p][1] = r1;
                    blf[2 * p + 1][0] = r2; blf[2 * p + 1][1] = r3;
                }
                // pass 1: hi*hi — 8 independent accumulators
                #pragma unroll
                for (int mt = 0; mt < 2; mt++) {
                    #pragma unroll
                    for (int nt = 0; nt < 4; nt++) {
                        MMA16816(acc[mt][nt][0], acc[mt][nt][1], acc[mt][nt][2], acc[mt][nt][3],
                                 ah[mt][0], ah[mt][1], ah[mt][2], ah[mt][3],
                                 bhf[nt][0], bhf[nt][1]);
                    }
                }
                // pass 2: lo*hi
                #pragma unroll
                for (int mt = 0; mt < 2; mt++) {
                    #pragma unroll
                    for (int nt = 0; nt < 4; nt++) {
                        MMA16816(acc[mt][nt][0], acc[mt][nt][1], acc[mt][nt][2], acc[mt][nt][3],
                                 al[mt][0], al[mt][1], al[mt][2], al[mt][3],
                                 bhf[nt][0], bhf[nt][1]);
                    }
                }
                // pass 3: hi*lo
                #pragma unroll
                for (int mt = 0; mt < 2; mt++) {
                    #pragma unroll
                    for (int nt = 0; nt < 4; nt++) {
                        MMA16816(acc[mt][nt][0], acc[mt][nt][1], acc[mt][nt][2], acc[mt][nt][3],
                                 ah[mt][0], ah[mt][1], ah[mt][2], ah[mt][3],
                                 blf[nt][0], blf[nt][1]);
                    }
                }
            }
            __syncthreads();
        }

        // register epilogue: scale + spatial act + top-5 insert (no smem)
        #pragma unroll
        for (int mt = 0; mt < 2; mt++) {
            #pragma unroll
            for (int nt = 0; nt < 4; nt++) {
                int m0 = mg + wm + nt * 8 + 2 * (lane & 3);
                float4 rr4 = *(const float4*)(&g_ra[m0]);   // rm0, act0, rm1, act1
                #pragma unroll
                for (int c = 0; c < 4; c++) {
                    int lst = mt * 2 + (c >> 1);
                    float rm  = (c & 1) ? rr4.z : rr4.x;
                    float act = (c & 1) ? rr4.w : rr4.y;
                    float v = fmaf(acc[mt][nt][c], fminf(rq[lst] * rm, 1e8f), act);
                    if (v > tv[lst][K_ - 1]) {
                        float cv = v;
                        int ci = m0 + (c & 1);
                        #pragma unroll
                        for (int s = 0; s < K_; s++) {
                            bool gt = cv > tv[lst][s];
                            float ov = tv[lst][s]; int oi = tix[lst][s];
                            tv[lst][s]  = gt ? cv : ov;
                            tix[lst][s] = gt ? ci : oi;
                            cv = gt ? ov : cv;
                            ci = gt ? oi : ci;
                        }
                    }
                }
            }
        }
    }

    // final merge via smem (aliases Q region)
    __syncthreads();
    float* mv = (float*)smbuf;
    int*   mi = (int*)(smbuf + 40960);
    int slot = (wid & 7) * 4 + (lane & 3);
    #pragma unroll
    for (int l = 0; l < 4; l++) {
        int q = wq + (l >> 1) * 16 + (l & 1) * 8 + (lane >> 2);
        #pragma unroll
        for (int s = 0; s < K_; s++) {
            mv[(q * 32 + slot) * K_ + s] = tv[l][s];
            mi[(q * 32 + slot) * K_ + s] = tix[l][s];
        }
    }
    __syncthreads();
    if (tid < BQ) {
        float bv[K_];
        int bi[K_];
        #pragma unroll
        for (int s = 0; s < K_; s++) { bv[s] = -3.4e38f; bi[s] = 0; }
        #pragma unroll 4
        for (int c = 0; c < 32 * K_; c++) {
            float v = mv[tid * 160 + c];
            int  ix = mi[tid * 160 + c];
            if (v > bv[K_ - 1]) {
                float cv = v;
                int ci = ix;
                #pragma unroll
                for (int s = 0; s < K_; s++) {
                    bool gt = cv > bv[s];
                    float ov = bv[s]; int oi = bi[s];
                    bv[s] = gt ? cv : ov;
                    bi[s] = gt ? ci : oi;
                    cv = gt ? ov : cv;
                    ci = gt ? oi : ci;
                }
            }
        }
        int b = qb + tid;
        #pragma unroll
        for (int s = 0; s < K_; s++) {
            g_candv[b * (CH_ * K_) + blockIdx.x * K_ + s] = bv[s];
            g_candi[b * (CH_ * K_) + blockIdx.x * K_ + s] = bi[s];
        }
    }
}

// ---------------- kernel 4: merge chunks -> final top-5 ----------------
__global__ void k_topkfinal() {
    int b = blockIdx.x * blockDim.x + threadIdx.x;
    if (b >= B_) return;
    float bv[K_];
    int bi[K_];
    #pragma unroll
    for (int s = 0; s < K_; s++) { bv[s] = -3.4e38f; bi[s] = 0; }
    for (int c = 0; c < CH_ * K_; c++) {
        float v = g_candv[b * (CH_ * K_) + c];
        int  ix = g_candi[b * (CH_ * K_) + c];
        if (v > bv[K_ - 1]) {
            float cv = v;
            int ci = ix;
            #pragma unroll
            for (int s = 0; s < K_; s++) {
                bool gt = cv > bv[s];
                float ov = bv[s]; int oi = bi[s];
                bv[s] = gt ? cv : ov;
                bi[s] = gt ? ci : oi;
                cv = gt ? ov : cv;
                ci = gt ? oi : ci;
            }
        }
    }
    #pragma unroll
    for (int s = 0; s < K_; s++) g_topk[b * K_ + s] = bi[s];
}

// ---------------- kernel 5: tiled GEMM (xproj rows + gate rows in one grid) ----------------
__global__ void __launch_bounds__(256)
k_gemm(const float* __restrict__ W_ih, const float* __restrict__ b_ih,
       const float* __restrict__ W_g, const float* __restrict__ b_g,
       const float* __restrict__ query, const float* __restrict__ mem) {
    __shared__ __align__(16) float a_s[KC * QTP];
    __shared__ __align__(16) float w_s[KC * MTP];
    int tid = threadIdx.x;
    int tx = tid & 15, ty = tid >> 4;
    int mode = (blockIdx.x < 6 * B_ / GBM) ? 0 : 1;
    int rb = (mode == 0) ? blockIdx.x * GBM : (blockIdx.x - 6 * B_ / GBM) * GBM;
    int hb = blockIdx.y * GBN;
    const float* W = (mode == 0) ? W_ih : W_g;
    const float* bias = (mode == 0) ? b_ih : b_g;

    float acc[4][8];
    #pragma unroll
    for (int i = 0; i < 4; i++) {
        #pragma unroll
        for (int j = 0; j < 8; j++) acc[i][j] = 0.f;
    }

    for (int kc = 0; kc < D_; kc += KC) {
        __syncthreads();
        #pragma unroll
        for (int l = 0; l < 2; l++) {
            int idx = tid + l * 256;
            int row = idx >> 3, k4 = idx & 7;
            int r = rb + row;
            const float* src;
            if (mode == 0) {
                int bq = r / 6;
                int tt = r - bq * 6;
                if (tt == 0) src = query + (size_t)bq * D_;
                else src = mem + (size_t)g_topk[bq * K_ + tt - 1] * D_;
            } else {
                src = query + (size_t)r * D_;
            }
            float4 v = *(const float4*)(src + kc + k4 * 4);
            int kl = k4 * 4;
            a_s[(kl + 0) * QTP + row] = v.x;
            a_s[(kl + 1) * QTP + row] = v.y;
            a_s[(kl + 2) * QTP + row] = v.z;
            a_s[(kl + 3) * QTP + row] = v.w;
        }
        #pragma unroll
        for (int l = 0; l < 4; l++) {
            int idx = tid + l * 256;
            int h = idx >> 3, k4 = idx & 7;
            float4 v = *(const float4*)(W + (size_t)(hb + h) * D_ + kc + k4 * 4);
            int kl = k4 * 4;
            w_s[(kl + 0) * MTP + h] = v.x;
            w_s[(kl + 1) * MTP + h] = v.y;
            w_s[(kl + 2) * MTP + h] = v.z;
            w_s[(kl + 3) * MTP + h] = v.w;
        }
        __syncthreads();

        #pragma unroll 8
        for (int k = 0; k < KC; k++) {
            float4 av  = *(const float4*)(a_s + k * QTP + ty * 4);
            float4 b0v = *(const float4*)(w_s + k * MTP + tx * 8);
            float4 b1v = *(const float4*)(w_s + k * MTP + tx * 8 + 4);
            float a[4];
            a[0] = av.x; a[1] = av.y; a[2] = av.z; a[3] = av.w;
            float bb[8];
            bb[0] = b0v.x; bb[1] = b0v.y; bb[2] = b0v.z; bb[3] = b0v.w;
            bb[4] = b1v.x; bb[5] = b1v.y; bb[6] = b1v.z; bb[7] = b1v.w;
            #pragma unroll
            for (int i = 0; i < 4; i++) {
                #pragma unroll
                for (int j = 0; j < 8; j++) acc[i][j] = fmaf(a[i], bb[j], acc[i][j]);
            }
        }
    }

    float* out = (mode == 0) ? g_xproj : g_gate;
    #pragma unroll
    for (int i = 0; i < 4; i++) {
        int r = rb + ty * 4 + i;
        #pragma unroll
        for (int j = 0; j < 8; j++) {
            int h = hb + tx * 8 + j;
            float v = acc[i][j] + bias[h];
            if (mode == 1) v = 1.f / (1.f + expf(-v));
            out[r * H_ + h] = v;
        }
    }
}

// ---------------- kernel 6: fused RNN (step0 + 5 steps + gated mix, 512 thr) ----------------
__global__ void __launch_bounds__(512) k_rnn(const float* __restrict__ Whh,
                                             const float* __restrict__ bhh,
                                             float* __restrict__ out) {
    extern __shared__ float rs[];
    float* h_s = rs;                  // RROWS rows * 384
    float* w_s = rs + RROWS * H_;     // 384 * RNS (w_s[h][kk])
    int tid = threadIdx.x;
    int r0 = blockIdx.x * RROWS;

    int rr[12], hh[12];
    #pragma unroll
    for (int o = 0; o < 12; o++) {
        int idx = o * 512 + tid;
        rr[o] = idx / H_;
        hh[o] = idx - rr[o] * H_;
    }

    // step 0: h = tanh(x0 + b_hh)
    #pragma unroll
    for (int o = 0; o < 12; o++)
        h_s[rr[o] * H_ + hh[o]] = tanhf(g_xproj[(r0 + rr[o]) * (6 * H_) + hh[o]] + bhh[hh[o]]);
    __syncthreads();

    for (int t = 1; t <= 5; t++) {
        float hn[12];
        #pragma unroll
        for (int o = 0; o < 12; o++)
            hn[o] = g_xproj[(r0 + rr[o]) * (6 * H_) + t * H_ + hh[o]] + bhh[hh[o]];

        for (int k0 = 0; k0 < H_; k0 += 32) {
            __syncthreads();
            for (int i = tid; i < 32 * H_; i += 512) {
                int kk = i & 31;
                int h = i >> 5;
                w_s[h * RNS + kk] = Whh[h * H_ + k0 + kk];
            }
            __syncthreads();
            #pragma unroll
            for (int o = 0; o < 12; o++) {
                const float4* wp = (const float4*)(w_s + hh[o] * RNS);
                const float4* hp = (const float4*)(h_s + rr[o] * H_ + k0);
                float a = 0.f;
                #pragma unroll
                for (int k4 = 0; k4 < 8; k4++) {
                    float4 w4 = wp[k4];
                    float4 h4 = hp[k4];
                    a = fmaf(w4.x, h4.x, a);
                    a = fmaf(w4.y, h4.y, a);
                    a = fmaf(w4.z, h4.z, a);
                    a = fmaf(w4.w, h4.w, a);
                }
                hn[o] += a;
            }
        }
        __syncthreads();
        if (t < 5) {
            #pragma unroll
            for (int o = 0; o < 12; o++) h_s[rr[o] * H_ + hh[o]] = tanhf(hn[o]);
            __syncthreads();
        } else {
            #pragma unroll
            for (int o = 0; o < 12; o++) {
                int gi = (r0 + rr[o]) * H_ + hh[o];
                float g = g_gate[gi];
                float direct = g_xproj[(r0 + rr[o]) * (6 * H_) + hh[o]];
                out[gi] = g * tanhf(hn[o]) + (1.f - g) * direct;
            }
        }
    }
}

// ---------------- launch ----------------
extern "C" void kernel_launch(void* const* d_in, const int* in_sizes, int n_in,
                              void* d_out, int out_size) {
    const float* query  = (const float*)d_in[0];
    const float* mem    = (const float*)d_in[1];
    const float* coords = (const float*)d_in[2];
    const float* sw     = (const float*)d_in[3];
    const float* W_ih   = (const float*)d_in[4];
    const float* b_ih   = (const float*)d_in[5];
    const float* W_hh   = (const float*)d_in[6];
    const float* b_hh   = (const float*)d_in[7];
    const float* W_g    = (const float*)d_in[8];
    const float* b_g    = (const float*)d_in[9];
    float* out = (float*)d_out;

    int nsplit = (M_ * D_ + B_ * D_) / 4;
    k_split<<<(nsplit + 255) / 256, 256>>>(query, mem);
    k_center<<<1, 128>>>(sw);
    k_prep<<<(M_ + B_) / 8, 256>>>(query, mem, coords);

    cudaFuncSetAttribute(k_main, cudaFuncAttributeMaxDynamicSharedMemorySize, SM_TOT);
    k_main<<<dim3(CH_, B_ / BQ), NTH, SM_TOT>>>();

    k_topkfinal<<<32, 32>>>();

    k_gemm<<<dim3(6 * B_ / GBM + B_ / GBM, H_ / GBN), 256>>>(W_ih, b_ih, W_g, b_g, query, mem);

    int rnn_smem = (RROWS * H_ + H_ * RNS) * 4;
    cudaFuncSetAttribute(k_rnn, cudaFuncAttributeMaxDynamicSharedMemorySize, rnn_smem);
    k_rnn<<<B_ / RROWS, 512, rnn_smem>>>(W_hh, b_hh, out);
}

// round 9
// speedup vs baseline: 1.7336x; 1.7336x over previous
#include <cuda_runtime.h>
#include <cuda_fp16.h>
#include <stdint.h>
#include <math.h>

#define B_  1024
#define M_  65536
#define D_  384
#define H_  384
#define K_  5

// ---- main kernel tiling ----
#define CH_   8
#define MCH   (M_/CH_)      // 8192
#define BQ    64
#define BN    256
#define BK    64
#define NT_   (MCH/BN)      // 32
#define NC_   (CH_*K_)      // 40 candidates per query

// smem byte offsets (k_main): Q hi 64*768=49152, then B hi double-buffered
#define SM_B   49152
#define BSTG   32768                 // 256 rows * 128B per stage
#define SM_TOT 114688                // 49152 + 2*32768

// ---- epilogue GEMM tiling ----
#define KC  32
#define QTP 68
#define MTP 132
#define GBM 64
#define GBN 128
#define RNS 36

// ---------------- ptx macros ----------------
#define CP_ASYNC16(dst, src) \
    asm volatile("cp.async.ca.shared.global [%0], [%1], 16;" :: "r"(dst), "l"(src))
#define CP_COMMIT() asm volatile("cp.async.commit_group;" ::: "memory")
#define CP_WAIT1()  asm volatile("cp.async.wait_group 1;" ::: "memory")
#define CP_WAIT0()  asm volatile("cp.async.wait_group 0;" ::: "memory")
#define LDM4(r0, r1, r2, r3, addr) \
    asm volatile("ldmatrix.sync.aligned.m8n8.x4.shared.b16 {%0,%1,%2,%3}, [%4];" \
                 : "=r"(r0), "=r"(r1), "=r"(r2), "=r"(r3) : "r"(addr))
#define MMA16816(c0, c1, c2, c3, a0, a1, a2, a3, b0, b1) \
    asm volatile("mma.sync.aligned.m16n8k16.row.col.f32.f16.f16.f32 " \
                 "{%0,%1,%2,%3}, {%4,%5,%6,%7}, {%8,%9}, {%0,%1,%2,%3};" \
                 : "+f"(c0), "+f"(c1), "+f"(c2), "+f"(c3) \
                 : "r"(a0), "r"(a1), "r"(a2), "r"(a3), "r"(b0), "r"(b1))

// ---------------- scratch (device globals; no allocation) ----------------
__device__ float  g_center[2];
__device__ float2 g_ra[M_];          // (1/||m||, act)
__device__ float  g_rq[B_];
__device__ float  g_candv[B_ * NC_];
__device__ int    g_candi[B_ * NC_];
__device__ int    g_topk[B_ * K_];
__device__ float  g_xproj[B_ * 6 * H_];
__device__ float  g_gate[B_ * H_];
__device__ __half g_mem_hi[M_ * D_];
__device__ __half g_q_hi[B_ * D_];

// ---------------- kernel 0: fp32 -> fp16 hi ----------------
__global__ void k_split(const float* __restrict__ q, const float* __restrict__ mem) {
    const int n4m = M_ * D_ / 4;
    const int n4q = B_ * D_ / 4;
    int i = blockIdx.x * blockDim.x + threadIdx.x;
    if (i >= n4m + n4q) return;
    float4 v;
    if (i < n4m) v = ((const float4*)mem)[i];
    else         v = ((const float4*)q)[i - n4m];
    float xs[4];
    xs[0] = v.x; xs[1] = v.y; xs[2] = v.z; xs[3] = v.w;
    uint32_t hw[4];
    #pragma unroll
    for (int k = 0; k < 4; k++) {
        __half hb = __float2half_rn(xs[k]);
        hw[k] = (uint32_t)__half_as_ushort(hb);
    }
    uint2 hp;
    hp.x = hw[0] | (hw[1] << 16); hp.y = hw[2] | (hw[3] << 16);
    if (i < n4m) ((uint2*)g_mem_hi)[i] = hp;
    else         ((uint2*)g_q_hi)[i - n4m] = hp;
}

// ---------------- kernel 1: center of spatial_weights ----------------
__global__ void k_center(const float* __restrict__ sw) {
    __shared__ float s0[128], s1[128];
    int i = threadIdx.x;
    float a = 0.f, b = 0.f;
    for (int j = i; j < H_; j += 128) { a += sw[j * 2]; b += sw[j * 2 + 1]; }
    s0[i] = a; s1[i] = b;
    __syncthreads();
    for (int off = 64; off > 0; off >>= 1) {
        if (i < off) { s0[i] += s0[i + off]; s1[i] += s1[i + off]; }
        __syncthreads();
    }
    if (i == 0) { g_center[0] = s0[0] / (float)H_; g_center[1] = s1[0] / (float)H_; }
}

// ---------------- kernel 2: per-row stats ----------------
__global__ void k_prep(const float* __restrict__ query,
                       const float* __restrict__ mem,
                       const float* __restrict__ coords) {
    int w = (blockIdx.x * blockDim.x + threadIdx.x) >> 5;
    int lane = threadIdx.x & 31;
    if (w < M_) {
        const float* row = mem + (size_t)w * D_;
        float ss = 0.f;
        #pragma unroll
        for (int j = 0; j < D_ / 32; j++) { float v = row[lane + j * 32]; ss += v * v; }
        #pragma unroll
        for (int o = 16; o; o >>= 1) ss += __shfl_xor_sync(0xffffffffu, ss, o);
        if (lane == 0) {
            float dx = coords[2 * w]     - g_center[0];
            float dy = coords[2 * w + 1] - g_center[1];
            float2 ra;
            ra.x = 1.f / sqrtf(ss);
            ra.y = 1.f / (1.f + sqrtf(dx * dx + dy * dy));
            g_ra[w] = ra;
        }
    } else if (w < M_ + B_) {
        int b = w - M_;
        const float* row = query + (size_t)b * D_;
        float ss = 0.f;
        #pragma unroll
        for (int j = 0; j < D_ / 32; j++) { float v = row[lane + j * 32]; ss += v * v; }
        #pragma unroll
        for (int o = 16; o; o >>= 1) ss += __shfl_xor_sync(0xffffffffu, ss, o);
        if (lane == 0) g_rq[b] = 1.f / sqrtf(ss);
    }
}

// ---------------- kernel 3: hi-only tensor GEMM + approx top-5 ----------------
__global__ void __launch_bounds__(256, 1) k_main() {
    extern __shared__ char smbuf[];
    uint32_t sbase;
    {
        uint64_t tmp = __cvta_generic_to_shared(smbuf);
        sbase = (uint32_t)tmp;
    }

    int tid = threadIdx.x;
    int lane = tid & 31;
    int wid = tid >> 5;
    int wq = (wid >> 2) * 32;       // 0 or 32
    int wm = (wid & 3) * 64;        // 0,64,128,192
    int qb = blockIdx.y * BQ;
    int mg0 = blockIdx.x * MCH;

    // resident Q hi (swizzled: 16B chunk c of row r -> chunk (c&~7)|((c^r)&7))
    for (int i = tid; i < BQ * 48; i += 256) {
        int r = i / 48;
        int c = i - r * 48;
        int cs = (c & ~7) | ((c ^ r) & 7);
        *(uint4*)(smbuf + r * 768 + cs * 16) = ((const uint4*)(g_q_hi + (qb + r) * D_))[c];
    }

    float rq[4];
    #pragma unroll
    for (int l = 0; l < 4; l++)
        rq[l] = g_rq[qb + wq + (l >> 1) * 16 + (l & 1) * 8 + (lane >> 2)];

    float tv[4][K_];
    int   tix[4][K_];
    #pragma unroll
    for (int l = 0; l < 4; l++) {
        #pragma unroll
        for (int s = 0; s < K_; s++) { tv[l][s] = -3.4e38f; tix[l][s] = 0; }
    }

    __syncthreads();

    // initial prefetch: tile 0, stage 0 -> buf 0
    {
        const __half* bh_g = g_mem_hi + (size_t)mg0 * D_;
        uint32_t dst = sbase + SM_B;
        #pragma unroll
        for (int l = 0; l < 8; l++) {
            int i = tid + l * 256;
            int r = i >> 3;
            int seg = i & 7;
            uint32_t doff = (uint32_t)(r * 128 + (((seg ^ r) & 7) << 4));
            CP_ASYNC16(dst + doff, (const void*)(bh_g + (size_t)r * D_ + seg * 8));
        }
        CP_COMMIT();
    }

    for (int t = 0; t < NT_; t++) {
        int mg = mg0 + t * BN;

        float acc[2][8][4];
        #pragma unroll
        for (int a = 0; a < 2; a++) {
            #pragma unroll
            for (int b = 0; b < 8; b++) {
                #pragma unroll
                for (int c = 0; c < 4; c++) acc[a][b][c] = 0.f;
            }
        }

        #pragma unroll
        for (int s = 0; s < 6; s++) {
            bool issue = (s < 5) || (t + 1 < NT_);
            if (issue) {
                int kc, mnext;
                uint32_t dst;
                if (s < 5) { kc = (s + 1) * BK; mnext = mg; dst = sbase + SM_B + (uint32_t)(((s + 1) & 1) * BSTG); }
                else       { kc = 0; mnext = mg + BN; dst = sbase + SM_B; }
                const __half* bh_g = g_mem_hi + (size_t)mnext * D_;
                #pragma unroll
                for (int l = 0; l < 8; l++) {
                    int i = tid + l * 256;
                    int r = i >> 3;
                    int seg = i & 7;
                    uint32_t doff = (uint32_t)(r * 128 + (((seg ^ r) & 7) << 4));
                    CP_ASYNC16(dst + doff, (const void*)(bh_g + (size_t)r * D_ + kc + seg * 8));
                }
                CP_COMMIT();
                CP_WAIT1();
            } else {
                CP_WAIT0();
            }
            __syncthreads();

            uint32_t bbuf = sbase + SM_B + (uint32_t)((s & 1) * BSTG);
            #pragma unroll
            for (int ks = 0; ks < 4; ks++) {
                int c16 = s * 8 + ks * 2 + (lane >> 4);
                uint32_t ah[2][4];
                #pragma unroll
                for (int mt = 0; mt < 2; mt++) {
                    int qrow = wq + mt * 16 + (lane & 15);
                    int cs = (c16 & ~7) | ((c16 ^ qrow) & 7);
                    uint32_t aoff = (uint32_t)(qrow * 768 + cs * 16);
                    LDM4(ah[mt][0], ah[mt][1], ah[mt][2], ah[mt][3], sbase + aoff);
                }
                uint32_t bhf[8][2];
                #pragma unroll
                for (int p = 0; p < 4; p++) {
                    int n = wm + p * 16 + ((lane >> 4) << 3) + (lane & 7);
                    int cb = ks * 2 + ((lane >> 3) & 1);
                    uint32_t boff = (uint32_t)(n * 128 + (((cb ^ n) & 7) << 4));
                    uint32_t r0, r1, r2, r3;
                    LDM4(r0, r1, r2, r3, bbuf + boff);
                    bhf[2 * p][0] = r0; bhf[2 * p][1] = r1;
                    bhf[2 * p + 1][0] = r2; bhf[2 * p + 1][1] = r3;
                }
                #pragma unroll
                for (int mt = 0; mt < 2; mt++) {
                    #pragma unroll
                    for (int nt = 0; nt < 8; nt++) {
                        MMA16816(acc[mt][nt][0], acc[mt][nt][1], acc[mt][nt][2], acc[mt][nt][3],
                                 ah[mt][0], ah[mt][1], ah[mt][2], ah[mt][3],
                                 bhf[nt][0], bhf[nt][1]);
                    }
                }
            }
            __syncthreads();
        }

        // register epilogue: approx scale + act + top-5 insert
        #pragma unroll
        for (int mt = 0; mt < 2; mt++) {
            #pragma unroll
            for (int nt = 0; nt < 8; nt++) {
                int m0 = mg + wm + nt * 8 + 2 * (lane & 3);
                float4 rr4 = *(const float4*)(&g_ra[m0]);   // rm0, act0, rm1, act1
                #pragma unroll
                for (int c = 0; c < 4; c++) {
                    int lst = mt * 2 + (c >> 1);
                    float rm  = (c & 1) ? rr4.z : rr4.x;
                    float act = (c & 1) ? rr4.w : rr4.y;
                    float v = fmaf(acc[mt][nt][c], fminf(rq[lst] * rm, 1e8f), act);
                    if (v > tv[lst][K_ - 1]) {
                        float cv = v;
                        int ci = m0 + (c & 1);
                        #pragma unroll
                        for (int s = 0; s < K_; s++) {
                            bool gt = cv > tv[lst][s];
                            float ov = tv[lst][s]; int oi = tix[lst][s];
                            tv[lst][s]  = gt ? cv : ov;
                            tix[lst][s] = gt ? ci : oi;
                            cv = gt ? ov : cv;
                            ci = gt ? oi : ci;
                        }
                    }
                }
            }
        }
    }

    // final merge via smem (aliases Q region)
    __syncthreads();
    float* mv = (float*)smbuf;
    int*   mi = (int*)(smbuf + 20480);
    int slot = (wid & 3) * 4 + (lane & 3);
    #pragma unroll
    for (int l = 0; l < 4; l++) {
        int q = wq + (l >> 1) * 16 + (l & 1) * 8 + (lane >> 2);
        #pragma unroll
        for (int s = 0; s < K_; s++) {
            mv[(q * 16 + slot) * K_ + s] = tv[l][s];
            mi[(q * 16 + slot) * K_ + s] = tix[l][s];
        }
    }
    __syncthreads();
    if (tid < BQ) {
        float bv[K_];
        int bi[K_];
        #pragma unroll
        for (int s = 0; s < K_; s++) { bv[s] = -3.4e38f; bi[s] = 0; }
        #pragma unroll 4
        for (int c = 0; c < 16 * K_; c++) {
            float v = mv[tid * 80 + c];
            int  ix = mi[tid * 80 + c];
            if (v > bv[K_ - 1]) {
                float cv = v;
                int ci = ix;
                #pragma unroll
                for (int s = 0; s < K_; s++) {
                    bool gt = cv > bv[s];
                    float ov = bv[s]; int oi = bi[s];
                    bv[s] = gt ? cv : ov;
                    bi[s] = gt ? ci : oi;
                    cv = gt ? ov : cv;
                    ci = gt ? oi : ci;
                }
            }
        }
        int b = qb + tid;
        #pragma unroll
        for (int s = 0; s < K_; s++) {
            g_candv[b * NC_ + blockIdx.x * K_ + s] = bv[s];
            g_candi[b * NC_ + blockIdx.x * K_ + s] = bi[s];
        }
    }
}

// ---------------- kernel 4: exact fp32 rescore of 40 candidates -> top-5 ----------------
__global__ void __launch_bounds__(256) k_rescore(const float* __restrict__ query,
                                                 const float* __restrict__ mem) {
    int warp = (blockIdx.x * blockDim.x + threadIdx.x) >> 5;
    int lane = threadIdx.x & 31;
    if (warp >= B_) return;
    int b = warp;

    float qv[12];
    #pragma unroll
    for (int j = 0; j < 12; j++) qv[j] = query[(size_t)b * D_ + lane + j * 32];
    float rq = g_rq[b];

    float bv[K_];
    int bi[K_];
    #pragma unroll
    for (int s = 0; s < K_; s++) { bv[s] = -3.4e38f; bi[s] = 0; }

    for (int c = 0; c < NC_; c++) {
        int idx = g_candi[b * NC_ + c];
        const float* mrow = mem + (size_t)idx * D_;
        float dot = 0.f;
        #pragma unroll
        for (int j = 0; j < 12; j++) dot = fmaf(qv[j], mrow[lane + j * 32], dot);
        #pragma unroll
        for (int o = 16; o; o >>= 1) dot += __shfl_xor_sync(0xffffffffu, dot, o);
        float2 ra = g_ra[idx];
        float v = fmaf(dot, fminf(rq * ra.x, 1e8f), ra.y);
        if (v > bv[K_ - 1]) {
            float cv = v;
            int ci = idx;
            #pragma unroll
            for (int s = 0; s < K_; s++) {
                bool gt = cv > bv[s];
                float ov = bv[s]; int oi = bi[s];
                bv[s] = gt ? cv : ov;
                bi[s] = gt ? ci : oi;
                cv = gt ? ov : cv;
                ci = gt ? oi : ci;
            }
        }
    }
    if (lane == 0) {
        #pragma unroll
        for (int s = 0; s < K_; s++) g_topk[b * K_ + s] = bi[s];
    }
}

// ---------------- kernel 5: tiled GEMM (xproj rows + gate rows in one grid) ----------------
__global__ void __launch_bounds__(256)
k_gemm(const float* __restrict__ W_ih, const float* __restrict__ b_ih,
       const float* __restrict__ W_g, const float* __restrict__ b_g,
       const float* __restrict__ query, const float* __restrict__ mem) {
    __shared__ __align__(16) float a_s[KC * QTP];
    __shared__ __align__(16) float w_s[KC * MTP];
    int tid = threadIdx.x;
    int tx = tid & 15, ty = tid >> 4;
    int mode = (blockIdx.x < 6 * B_ / GBM) ? 0 : 1;
    int rb = (mode == 0) ? blockIdx.x * GBM : (blockIdx.x - 6 * B_ / GBM) * GBM;
    int hb = blockIdx.y * GBN;
    const float* W = (mode == 0) ? W_ih : W_g;
    const float* bias = (mode == 0) ? b_ih : b_g;

    float acc[4][8];
    #pragma unroll
    for (int i = 0; i < 4; i++) {
        #pragma unroll
        for (int j = 0; j < 8; j++) acc[i][j] = 0.f;
    }

    for (int kc = 0; kc < D_; kc += KC) {
        __syncthreads();
        #pragma unroll
        for (int l = 0; l < 2; l++) {
            int idx = tid + l * 256;
            int row = idx >> 3, k4 = idx & 7;
            int r = rb + row;
            const float* src;
            if (mode == 0) {
                int bq = r / 6;
                int tt = r - bq * 6;
                if (tt == 0) src = query + (size_t)bq * D_;
                else src = mem + (size_t)g_topk[bq * K_ + tt - 1] * D_;
            } else {
                src = query + (size_t)r * D_;
            }
            float4 v = *(const float4*)(src + kc + k4 * 4);
            int kl = k4 * 4;
            a_s[(kl + 0) * QTP + row] = v.x;
            a_s[(kl + 1) * QTP + row] = v.y;
            a_s[(kl + 2) * QTP + row] = v.z;
            a_s[(kl + 3) * QTP + row] = v.w;
        }
        #pragma unroll
        for (int l = 0; l < 4; l++) {
            int idx = tid + l * 256;
            int h = idx >> 3, k4 = idx & 7;
            float4 v = *(const float4*)(W + (size_t)(hb + h) * D_ + kc + k4 * 4);
            int kl = k4 * 4;
            w_s[(kl + 0) * MTP + h] = v.x;
            w_s[(kl + 1) * MTP + h] = v.y;
            w_s[(kl + 2) * MTP + h] = v.z;
            w_s[(kl + 3) * MTP + h] = v.w;
        }
        __syncthreads();

        #pragma unroll 8
        for (int k = 0; k < KC; k++) {
            float4 av  = *(const float4*)(a_s + k * QTP + ty * 4);
            float4 b0v = *(const float4*)(w_s + k * MTP + tx * 8);
            float4 b1v = *(const float4*)(w_s + k * MTP + tx * 8 + 4);
            float a[4];
            a[0] = av.x; a[1] = av.y; a[2] = av.z; a[3] = av.w;
            float bb[8];
            bb[0] = b0v.x; bb[1] = b0v.y; bb[2] = b0v.z; bb[3] = b0v.w;
            bb[4] = b1v.x; bb[5] = b1v.y; bb[6] = b1v.z; bb[7] = b1v.w;
            #pragma unroll
            for (int i = 0; i < 4; i++) {
                #pragma unroll
                for (int j = 0; j < 8; j++) acc[i][j] = fmaf(a[i], bb[j], acc[i][j]);
            }
        }
    }

    float* out = (mode == 0) ? g_xproj : g_gate;
    #pragma unroll
    for (int i = 0; i < 4; i++) {
        int r = rb + ty * 4 + i;
        #pragma unroll
        for (int j = 0; j < 8; j++) {
            int h = hb + tx * 8 + j;
            float v = acc[i][j] + bias[h];
            if (mode == 1) v = 1.f / (1.f + expf(-v));
            out[r * H_ + h] = v;
        }
    }
}

// ---------------- kernel 6: fused RNN (round-6 best config) ----------------
__global__ void __launch_bounds__(256) k_rnn(const float* __restrict__ Whh,
                                             const float* __restrict__ bhh,
                                             float* __restrict__ out) {
    extern __shared__ float rs[];
    float* h_s = rs;
    float* w_s = rs + 8 * H_;
    int tid = threadIdx.x;
    int r0 = blockIdx.x * 8;

    int rr[12], hh[12];
    #pragma unroll
    for (int o = 0; o < 12; o++) {
        int idx = o * 256 + tid;
        rr[o] = idx / H_;
        hh[o] = idx - rr[o] * H_;
    }

    #pragma unroll
    for (int o = 0; o < 12; o++)
        h_s[rr[o] * H_ + hh[o]] = tanhf(g_xproj[(r0 + rr[o]) * (6 * H_) + hh[o]] + bhh[hh[o]]);
    __syncthreads();

    for (int t = 1; t <= 5; t++) {
        float hn[12];
        #pragma unroll
        for (int o = 0; o < 12; o++)
            hn[o] = g_xproj[(r0 + rr[o]) * (6 * H_) + t * H_ + hh[o]] + bhh[hh[o]];

        for (int k0 = 0; k0 < H_; k0 += 32) {
            __syncthreads();
            for (int i = tid; i < 32 * H_; i += 256) {
                int kk = i & 31;
                int h = i >> 5;
                w_s[h * RNS + kk] = Whh[h * H_ + k0 + kk];
            }
            __syncthreads();
            #pragma unroll
            for (int o = 0; o < 12; o++) {
                const float4* wp = (const float4*)(w_s + hh[o] * RNS);
                const float4* hp = (const float4*)(h_s + rr[o] * H_ + k0);
                float a = 0.f;
                #pragma unroll
                for (int k4 = 0; k4 < 8; k4++) {
                    float4 w4 = wp[k4];
                    float4 h4 = hp[k4];
                    a = fmaf(w4.x, h4.x, a);
                    a = fmaf(w4.y, h4.y, a);
                    a = fmaf(w4.z, h4.z, a);
                    a = fmaf(w4.w, h4.w, a);
                }
                hn[o] += a;
            }
        }
        __syncthreads();
        if (t < 5) {
            #pragma unroll
            for (int o = 0; o < 12; o++) h_s[rr[o] * H_ + hh[o]] = tanhf(hn[o]);
            __syncthreads();
        } else {
            #pragma unroll
            for (int o = 0; o < 12; o++) {
                int gi = (r0 + rr[o]) * H_ + hh[o];
                float g = g_gate[gi];
                float direct = g_xproj[(r0 + rr[o]) * (6 * H_) + hh[o]];
                out[gi] = g * tanhf(hn[o]) + (1.f - g) * direct;
            }
        }
    }
}

// ---------------- launch ----------------
extern "C" void kernel_launch(void* const* d_in, const int* in_sizes, int n_in,
                              void* d_out, int out_size) {
    const float* query  = (const float*)d_in[0];
    const float* mem    = (const float*)d_in[1];
    const float* coords = (const float*)d_in[2];
    const float* sw     = (const float*)d_in[3];
    const float* W_ih   = (const float*)d_in[4];
    const float* b_ih   = (const float*)d_in[5];
    const float* W_hh   = (const float*)d_in[6];
    const float* b_hh   = (const float*)d_in[7];
    const float* W_g    = (const float*)d_in[8];
    const float* b_g    = (const float*)d_in[9];
    float* out = (float*)d_out;

    int nsplit = (M_ * D_ + B_ * D_) / 4;
    k_split<<<(nsplit + 255) / 256, 256>>>(query, mem);
    k_center<<<1, 128>>>(sw);
    k_prep<<<(M_ + B_) / 8, 256>>>(query, mem, coords);

    cudaFuncSetAttribute(k_main, cudaFuncAttributeMaxDynamicSharedMemorySize, SM_TOT);
    k_main<<<dim3(CH_, B_ / BQ), 256, SM_TOT>>>();

    k_rescore<<<B_ / 8, 256>>>(query, mem);

    k_gemm<<<dim3(6 * B_ / GBM + B_ / GBM, H_ / GBN), 256>>>(W_ih, b_ih, W_g, b_g, query, mem);

    int rnn_smem = (8 * H_ + H_ * RNS) * 4;
    cudaFuncSetAttribute(k_rnn, cudaFuncAttributeMaxDynamicSharedMemorySize, rnn_smem);
    k_rnn<<<B_ / 8, 256, rnn_smem>>>(W_hh, b_hh, out);
}

// round 11
// speedup vs baseline: 1.8544x; 1.0696x over previous
#include <cuda_runtime.h>
#include <cuda_fp16.h>
#include <stdint.h>
#include <math.h>

#define B_  1024
#define M_  65536
#define D_  384
#define H_  384
#define K_  5

// ---- main kernel tiling ----
#define CH_   16
#define MCH   (M_/CH_)      // 4096
#define BQ    64
#define BN    128
#define BK    64
#define NT_   (MCH/BN)      // 32
#define NC_   (CH_*K_)      // 80 candidates per query

// smem byte offsets (k_main): Q hi 64*768=49152, then B hi double-buffered
#define SM_B   49152
#define BSTG   16384                 // 128 rows * 128B per stage
#define SM_TOT 81920                 // 49152 + 2*16384

// ---- epilogue GEMM tiling ----
#define KC  32
#define QTP 68
#define MTP 132
#define GBM 64
#define GBN 128
#define RNS 36

// ---------------- ptx macros ----------------
#define CP_ASYNC16(dst, src) \
    asm volatile("cp.async.ca.shared.global [%0], [%1], 16;" :: "r"(dst), "l"(src))
#define CP_COMMIT() asm volatile("cp.async.commit_group;" ::: "memory")
#define CP_WAIT1()  asm volatile("cp.async.wait_group 1;" ::: "memory")
#define CP_WAIT0()  asm volatile("cp.async.wait_group 0;" ::: "memory")
#define LDM4(r0, r1, r2, r3, addr) \
    asm volatile("ldmatrix.sync.aligned.m8n8.x4.shared.b16 {%0,%1,%2,%3}, [%4];" \
                 : "=r"(r0), "=r"(r1), "=r"(r2), "=r"(r3) : "r"(addr))
#define MMA16816(c0, c1, c2, c3, a0, a1, a2, a3, b0, b1) \
    asm volatile("mma.sync.aligned.m16n8k16.row.col.f32.f16.f16.f32 " \
                 "{%0,%1,%2,%3}, {%4,%5,%6,%7}, {%8,%9}, {%0,%1,%2,%3};" \
                 : "+f"(c0), "+f"(c1), "+f"(c2), "+f"(c3) \
                 : "r"(a0), "r"(a1), "r"(a2), "r"(a3), "r"(b0), "r"(b1))

// ---------------- scratch (device globals; no allocation) ----------------
__device__ float  g_center[2];
__device__ float2 g_ra[M_];          // (1/||m||, act)
__device__ float  g_rq[B_];
__device__ float  g_candv[B_ * NC_];
__device__ int    g_candi[B_ * NC_];
__device__ int    g_topk[B_ * K_];
__device__ float  g_xproj[B_ * 6 * H_];
__device__ float  g_gate[B_ * H_];
__device__ __half g_mem_hi[M_ * D_];
__device__ __half g_q_hi[B_ * D_];

// ---------------- kernel 1: center of spatial_weights ----------------
__global__ void k_center(const float* __restrict__ sw) {
    __shared__ float s0[128], s1[128];
    int i = threadIdx.x;
    float a = 0.f, b = 0.f;
    for (int j = i; j < H_; j += 128) { a += sw[j * 2]; b += sw[j * 2 + 1]; }
    s0[i] = a; s1[i] = b;
    __syncthreads();
    for (int off = 64; off > 0; off >>= 1) {
        if (i < off) { s0[i] += s0[i + off]; s1[i] += s1[i + off]; }
        __syncthreads();
    }
    if (i == 0) { g_center[0] = s0[0] / (float)H_; g_center[1] = s1[0] / (float)H_; }
}

// ---------------- kernel 2: fused split + per-row stats (single pass) ----------------
__global__ void k_prep(const float* __restrict__ query,
                       const float* __restrict__ mem,
                       const float* __restrict__ coords) {
    int w = (blockIdx.x * blockDim.x + threadIdx.x) >> 5;
    int lane = threadIdx.x & 31;
    if (w < M_) {
        const float2* row = (const float2*)(mem + (size_t)w * D_);
        __half2* dst = (__half2*)(g_mem_hi + (size_t)w * D_);
        float ss = 0.f;
        #pragma unroll
        for (int j = 0; j < 6; j++) {
            float2 v = row[lane + j * 32];
            ss = fmaf(v.x, v.x, fmaf(v.y, v.y, ss));
            dst[lane + j * 32] = __floats2half2_rn(v.x, v.y);
        }
        #pragma unroll
        for (int o = 16; o; o >>= 1) ss += __shfl_xor_sync(0xffffffffu, ss, o);
        if (lane == 0) {
            float dx = coords[2 * w]     - g_center[0];
            float dy = coords[2 * w + 1] - g_center[1];
            float2 ra;
            ra.x = 1.f / sqrtf(ss);
            ra.y = 1.f / (1.f + sqrtf(dx * dx + dy * dy));
            g_ra[w] = ra;
        }
    } else if (w < M_ + B_) {
        int b = w - M_;
        const float2* row = (const float2*)(query + (size_t)b * D_);
        __half2* dst = (__half2*)(g_q_hi + (size_t)b * D_);
        float ss = 0.f;
        #pragma unroll
        for (int j = 0; j < 6; j++) {
            float2 v = row[lane + j * 32];
            ss = fmaf(v.x, v.x, fmaf(v.y, v.y, ss));
            dst[lane + j * 32] = __floats2half2_rn(v.x, v.y);
        }
        #pragma unroll
        for (int o = 16; o; o >>= 1) ss += __shfl_xor_sync(0xffffffffu, ss, o);
        if (lane == 0) g_rq[b] = 1.f / sqrtf(ss);
    }
}

// ---------------- kernel 3: hi-only tensor GEMM + approx top-5 (2 CTA/SM) ----------------
__global__ void __launch_bounds__(256, 2) k_main() {
    extern __shared__ char smbuf[];
    uint32_t sbase;
    {
        uint64_t tmp = __cvta_generic_to_shared(smbuf);
        sbase = (uint32_t)tmp;
    }

    int tid = threadIdx.x;
    int lane = tid & 31;
    int wid = tid >> 5;
    int wq = (wid >> 2) * 32;       // 0 or 32
    int wm = (wid & 3) * 32;        // 0,32,64,96
    int qb = blockIdx.y * BQ;
    int mg0 = blockIdx.x * MCH;

    // resident Q hi (swizzled: 16B chunk c of row r -> chunk (c&~7)|((c^r)&7))
    for (int i = tid; i < BQ * 48; i += 256) {
        int r = i / 48;
        int c = i - r * 48;
        int cs = (c & ~7) | ((c ^ r) & 7);
        *(uint4*)(smbuf + r * 768 + cs * 16) = ((const uint4*)(g_q_hi + (qb + r) * D_))[c];
    }

    float rq[4];
    #pragma unroll
    for (int l = 0; l < 4; l++)
        rq[l] = g_rq[qb + wq + (l >> 1) * 16 + (l & 1) * 8 + (lane >> 2)];

    float tv[4][K_];
    int   tix[4][K_];
    #pragma unroll
    for (int l = 0; l < 4; l++) {
        #pragma unroll
        for (int s = 0; s < K_; s++) { tv[l][s] = -3.4e38f; tix[l][s] = 0; }
    }

    __syncthreads();

    // initial prefetch: tile 0, stage 0 -> buf 0
    {
        const __half* bh_g = g_mem_hi + (size_t)mg0 * D_;
        uint32_t dst = sbase + SM_B;
        #pragma unroll
        for (int l = 0; l < 4; l++) {
            int i = tid + l * 256;
            int r = i >> 3;
            int seg = i & 7;
            uint32_t doff = (uint32_t)(r * 128 + (((seg ^ r) & 7) << 4));
            CP_ASYNC16(dst + doff, (const void*)(bh_g + (size_t)r * D_ + seg * 8));
        }
        CP_COMMIT();
    }

    for (int t = 0; t < NT_; t++) {
        int mg = mg0 + t * BN;

        float acc[2][4][4];
        #pragma unroll
        for (int a = 0; a < 2; a++) {
            #pragma unroll
            for (int b = 0; b < 4; b++) {
                #pragma unroll
                for (int c = 0; c < 4; c++) acc[a][b][c] = 0.f;
            }
        }

        #pragma unroll
        for (int s = 0; s < 6; s++) {
            bool issue = (s < 5) || (t + 1 < NT_);
            if (issue) {
                int kc, mnext;
                uint32_t dst;
                if (s < 5) { kc = (s + 1) * BK; mnext = mg; dst = sbase + SM_B + (uint32_t)(((s + 1) & 1) * BSTG); }
                else       { kc = 0; mnext = mg + BN; dst = sbase + SM_B; }
                const __half* bh_g = g_mem_hi + (size_t)mnext * D_;
                #pragma unroll
                for (int l = 0; l < 4; l++) {
                    int i = tid + l * 256;
                    int r = i >> 3;
                    int seg = i & 7;
                    uint32_t doff = (uint32_t)(r * 128 + (((seg ^ r) & 7) << 4));
                    CP_ASYNC16(dst + doff, (const void*)(bh_g + (size_t)r * D_ + kc + seg * 8));
                }
                CP_COMMIT();
                CP_WAIT1();
            } else {
                CP_WAIT0();
            }
            __syncthreads();

            uint32_t bbuf = sbase + SM_B + (uint32_t)((s & 1) * BSTG);
            #pragma unroll
            for (int ks = 0; ks < 4; ks++) {
                int c16 = s * 8 + ks * 2 + (lane >> 4);
                uint32_t ah[2][4];
                #pragma unroll
                for (int mt = 0; mt < 2; mt++) {
                    int qrow = wq + mt * 16 + (lane & 15);
                    int cs = (c16 & ~7) | ((c16 ^ qrow) & 7);
                    uint32_t aoff = (uint32_t)(qrow * 768 + cs * 16);
                    LDM4(ah[mt][0], ah[mt][1], ah[mt][2], ah[mt][3], sbase + aoff);
                }
                uint32_t bhf[4][2];
                #pragma unroll
                for (int p = 0; p < 2; p++) {
                    int n = wm + p * 16 + ((lane >> 4) << 3) + (lane & 7);
                    int cb = ks * 2 + ((lane >> 3) & 1);
                    uint32_t boff = (uint32_t)(n * 128 + (((cb ^ n) & 7) << 4));
                    uint32_t r0, r1, r2, r3;
                    LDM4(r0, r1, r2, r3, bbuf + boff);
                    bhf[2 * p][0] = r0; bhf[2 * p][1] = r1;
                    bhf[2 * p + 1][0] = r2; bhf[2 * p + 1][1] = r3;
                }
                #pragma unroll
                for (int mt = 0; mt < 2; mt++) {
                    #pragma unroll
                    for (int nt = 0; nt < 4; nt++) {
                        MMA16816(acc[mt][nt][0], acc[mt][nt][1], acc[mt][nt][2], acc[mt][nt][3],
                                 ah[mt][0], ah[mt][1], ah[mt][2], ah[mt][3],
                                 bhf[nt][0], bhf[nt][1]);
                    }
                }
            }
            __syncthreads();
        }

        // register epilogue: approx scale + act + top-5 insert
        #pragma unroll
        for (int mt = 0; mt < 2; mt++) {
            #pragma unroll
            for (int nt = 0; nt < 4; nt++) {
                int m0 = mg + wm + nt * 8 + 2 * (lane & 3);
                float4 rr4 = *(const float4*)(&g_ra[m0]);   // rm0, act0, rm1, act1
                #pragma unroll
                for (int c = 0; c < 4; c++) {
                    int lst = mt * 2 + (c >> 1);
                    float rm  = (c & 1) ? rr4.z : rr4.x;
                    float act = (c & 1) ? rr4.w : rr4.y;
                    float v = fmaf(acc[mt][nt][c], fminf(rq[lst] * rm, 1e8f), act);
                    if (v > tv[lst][K_ - 1]) {
                        float cv = v;
                        int ci = m0 + (c & 1);
                        #pragma unroll
                        for (int s = 0; s < K_; s++) {
                            bool gt = cv > tv[lst][s];
                            float ov = tv[lst][s]; int oi = tix[lst][s];
                            tv[lst][s]  = gt ? cv : ov;
                            tix[lst][s] = gt ? ci : oi;
                            cv = gt ? ov : cv;
                            ci = gt ? oi : ci;
                        }
                    }
                }
            }
        }
    }

    // final merge via smem (aliases Q region)
    __syncthreads();
    float* mv = (float*)smbuf;
    int*   mi = (int*)(smbuf + 20480);
    int slot = (wid & 3) * 4 + (lane & 3);
    #pragma unroll
    for (int l = 0; l < 4; l++) {
        int q = wq + (l >> 1) * 16 + (l & 1) * 8 + (lane >> 2);
        #pragma unroll
        for (int s = 0; s < K_; s++) {
            mv[(q * 16 + slot) * K_ + s] = tv[l][s];
            mi[(q * 16 + slot) * K_ + s] = tix[l][s];
        }
    }
    __syncthreads();
    if (tid < BQ) {
        float bv[K_];
        int bi[K_];
        #pragma unroll
        for (int s = 0; s < K_; s++) { bv[s] = -3.4e38f; bi[s] = 0; }
        #pragma unroll 4
        for (int c = 0; c < 16 * K_; c++) {
            float v = mv[tid * 80 + c];
            int  ix = mi[tid * 80 + c];
            if (v > bv[K_ - 1]) {
                float cv = v;
                int ci = ix;
                #pragma unroll
                for (int s = 0; s < K_; s++) {
                    bool gt = cv > bv[s];
                    float ov = bv[s]; int oi = bi[s];
                    bv[s] = gt ? cv : ov;
                    bi[s] = gt ? ci : oi;
                    cv = gt ? ov : cv;
                    ci = gt ? oi : ci;
                }
            }
        }
        int b = qb + tid;
        #pragma unroll
        for (int s = 0; s < K_; s++) {
            g_candv[b * NC_ + blockIdx.x * K_ + s] = bv[s];
            g_candi[b * NC_ + blockIdx.x * K_ + s] = bi[s];
        }
    }
}

// ---------------- kernel 4: exact fp32 rescore of 80 candidates -> top-5 ----------------
__global__ void __launch_bounds__(256) k_rescore(const float* __restrict__ query,
                                                 const float* __restrict__ mem) {
    int warp = (blockIdx.x * blockDim.x + threadIdx.x) >> 5;
    int lane = threadIdx.x & 31;
    if (warp >= B_) return;
    int b = warp;

    float qv[12];
    #pragma unroll
    for (int j = 0; j < 12; j++) qv[j] = query[(size_t)b * D_ + lane + j * 32];
    float rq = g_rq[b];

    float bv[K_];
    int bi[K_];
    #pragma unroll
    for (int s = 0; s < K_; s++) { bv[s] = -3.4e38f; bi[s] = 0; }

    for (int c = 0; c < NC_; c++) {
        int idx = g_candi[b * NC_ + c];
        const float* mrow = mem + (size_t)idx * D_;
        float dot = 0.f;
        #pragma unroll
        for (int j = 0; j < 12; j++) dot = fmaf(qv[j], mrow[lane + j * 32], dot);
        #pragma unroll
        for (int o = 16; o; o >>= 1) dot += __shfl_xor_sync(0xffffffffu, dot, o);
        float2 ra = g_ra[idx];
        float v = fmaf(dot, fminf(rq * ra.x, 1e8f), ra.y);
        if (v > bv[K_ - 1]) {
            float cv = v;
            int ci = idx;
            #pragma unroll
            for (int s = 0; s < K_; s++) {
                bool gt = cv > bv[s];
                float ov = bv[s]; int oi = bi[s];
                bv[s] = gt ? cv : ov;
                bi[s] = gt ? ci : oi;
                cv = gt ? ov : cv;
                ci = gt ? oi : ci;
            }
        }
    }
    if (lane == 0) {
        #pragma unroll
        for (int s = 0; s < K_; s++) g_topk[b * K_ + s] = bi[s];
    }
}

// ---------------- kernel 5: tiled GEMM (xproj rows + gate rows in one grid) ----------------
__global__ void __launch_bounds__(256)
k_gemm(const float* __restrict__ W_ih, const float* __restrict__ b_ih,
       const float* __restrict__ W_g, const float* __restrict__ b_g,
       const float* __restrict__ query, const float* __restrict__ mem) {
    __shared__ __align__(16) float a_s[KC * QTP];
    __shared__ __align__(16) float w_s[KC * MTP];
    int tid = threadIdx.x;
    int tx = tid & 15, ty = tid >> 4;
    int mode = (blockIdx.x < 6 * B_ / GBM) ? 0 : 1;
    int rb = (mode == 0) ? blockIdx.x * GBM : (blockIdx.x - 6 * B_ / GBM) * GBM;
    int hb = blockIdx.y * GBN;
    const float* W = (mode == 0) ? W_ih : W_g;
    const float* bias = (mode == 0) ? b_ih : b_g;

    float acc[4][8];
    #pragma unroll
    for (int i = 0; i < 4; i++) {
        #pragma unroll
        for (int j = 0; j < 8; j++) acc[i][j] = 0.f;
    }

    for (int kc = 0; kc < D_; kc += KC) {
        __syncthreads();
        #pragma unroll
        for (int l = 0; l < 2; l++) {
            int idx = tid + l * 256;
            int row = idx >> 3, k4 = idx & 7;
            int r = rb + row;
            const float* src;
            if (mode == 0) {
                int bq = r / 6;
                int tt = r - bq * 6;
                if (tt == 0) src = query + (size_t)bq * D_;
                else src = mem + (size_t)g_topk[bq * K_ + tt - 1] * D_;
            } else {
                src = query + (size_t)r * D_;
            }
            float4 v = *(const float4*)(src + kc + k4 * 4);
            int kl = k4 * 4;
            a_s[(kl + 0) * QTP + row] = v.x;
            a_s[(kl + 1) * QTP + row] = v.y;
            a_s[(kl + 2) * QTP + row] = v.z;
            a_s[(kl + 3) * QTP + row] = v.w;
        }
        #pragma unroll
        for (int l = 0; l < 4; l++) {
            int idx = tid + l * 256;
            int h = idx >> 3, k4 = idx & 7;
            float4 v = *(const float4*)(W + (size_t)(hb + h) * D_ + kc + k4 * 4);
            int kl = k4 * 4;
            w_s[(kl + 0) * MTP + h] = v.x;
            w_s[(kl + 1) * MTP + h] = v.y;
            w_s[(kl + 2) * MTP + h] = v.z;
            w_s[(kl + 3) * MTP + h] = v.w;
        }
        __syncthreads();

        #pragma unroll 8
        for (int k = 0; k < KC; k++) {
            float4 av  = *(const float4*)(a_s + k * QTP + ty * 4);
            float4 b0v = *(const float4*)(w_s + k * MTP + tx * 8);
            float4 b1v = *(const float4*)(w_s + k * MTP + tx * 8 + 4);
            float a[4];
            a[0] = av.x; a[1] = av.y; a[2] = av.z; a[3] = av.w;
            float bb[8];
            bb[0] = b0v.x; bb[1] = b0v.y; bb[2] = b0v.z; bb[3] = b0v.w;
            bb[4] = b1v.x; bb[5] = b1v.y; bb[6] = b1v.z; bb[7] = b1v.w;
            #pragma unroll
            for (int i = 0; i < 4; i++) {
                #pragma unroll
                for (int j = 0; j < 8; j++) acc[i][j] = fmaf(a[i], bb[j], acc[i][j]);
            }
        }
    }

    float* out = (mode == 0) ? g_xproj : g_gate;
    #pragma unroll
    for (int i = 0; i < 4; i++) {
        int r = rb + ty * 4 + i;
        #pragma unroll
        for (int j = 0; j < 8; j++) {
            int h = hb + tx * 8 + j;
            float v = acc[i][j] + bias[h];
            if (mode == 1) v = 1.f / (1.f + expf(-v));
            out[r * H_ + h] = v;
        }
    }
}

// ---------------- kernel 6: fused RNN ----------------
__global__ void __launch_bounds__(256) k_rnn(const float* __restrict__ Whh,
                                             const float* __restrict__ bhh,
                                             float* __restrict__ out) {
    extern __shared__ float rs[];
    float* h_s = rs;
    float* w_s = rs + 8 * H_;
    int tid = threadIdx.x;
    int r0 = blockIdx.x * 8;

    int rr[12], hh[12];
    #pragma unroll
    for (int o = 0; o < 12; o++) {
        int idx = o * 256 + tid;
        rr[o] = idx / H_;
        hh[o] = idx - rr[o] * H_;
    }

    #pragma unroll
    for (int o = 0; o < 12; o++)
        h_s[rr[o] * H_ + hh[o]] = tanhf(g_xproj[(r0 + rr[o]) * (6 * H_) + hh[o]] + bhh[hh[o]]);
    __syncthreads();

    for (int t = 1; t <= 5; t++) {
        float hn[12];
        #pragma unroll
        for (int o = 0; o < 12; o++)
            hn[o] = g_xproj[(r0 + rr[o]) * (6 * H_) + t * H_ + hh[o]] + bhh[hh[o]];

        for (int k0 = 0; k0 < H_; k0 += 32) {
            __syncthreads();
            for (int i = tid; i < 32 * H_; i += 256) {
                int kk = i & 31;
                int h = i >> 5;
                w_s[h * RNS + kk] = Whh[h * H_ + k0 + kk];
            }
            __syncthreads();
            #pragma unroll
            for (int o = 0; o < 12; o++) {
                const float4* wp = (const float4*)(w_s + hh[o] * RNS);
                const float4* hp = (const float4*)(h_s + rr[o] * H_ + k0);
                float a = 0.f;
                #pragma unroll
                for (int k4 = 0; k4 < 8; k4++) {
                    float4 w4 = wp[k4];
                    float4 h4 = hp[k4];
                    a = fmaf(w4.x, h4.x, a);
                    a = fmaf(w4.y, h4.y, a);
                    a = fmaf(w4.z, h4.z, a);
                    a = fmaf(w4.w, h4.w, a);
                }
                hn[o] += a;
            }
        }
        __syncthreads();
        if (t < 5) {
            #pragma unroll
            for (int o = 0; o < 12; o++) h_s[rr[o] * H_ + hh[o]] = tanhf(hn[o]);
            __syncthreads();
        } else {
            #pragma unroll
            for (int o = 0; o < 12; o++) {
                int gi = (r0 + rr[o]) * H_ + hh[o];
                float g = g_gate[gi];
                float direct = g_xproj[(r0 + rr[o]) * (6 * H_) + hh[o]];
                out[gi] = g * tanhf(hn[o]) + (1.f - g) * direct;
            }
        }
    }
}

// ---------------- launch ----------------
extern "C" void kernel_launch(void* const* d_in, const int* in_sizes, int n_in,
                              void* d_out, int out_size) {
    const float* query  = (const float*)d_in[0];
    const float* mem    = (const float*)d_in[1];
    const float* coords = (const float*)d_in[2];
    const float* sw     = (const float*)d_in[3];
    const float* W_ih   = (const float*)d_in[4];
    const float* b_ih   = (const float*)d_in[5];
    const float* W_hh   = (const float*)d_in[6];
    const float* b_hh   = (const float*)d_in[7];
    const float* W_g    = (const float*)d_in[8];
    const float* b_g    = (const float*)d_in[9];
    float* out = (float*)d_out;

    k_center<<<1, 128>>>(sw);
    k_prep<<<(M_ + B_) / 8, 256>>>(query, mem, coords);

    cudaFuncSetAttribute(k_main, cudaFuncAttributeMaxDynamicSharedMemorySize, SM_TOT);
    k_main<<<dim3(CH_, B_ / BQ), 256, SM_TOT>>>();

    k_rescore<<<B_ / 8, 256>>>(query, mem);

    k_gemm<<<dim3(6 * B_ / GBM + B_ / GBM, H_ / GBN), 256>>>(W_ih, b_ih, W_g, b_g, query, mem);

    int rnn_smem = (8 * H_ + H_ * RNS) * 4;
    cudaFuncSetAttribute(k_rnn, cudaFuncAttributeMaxDynamicSharedMemorySize, rnn_smem);
    k_rnn<<<B_ / 8, 256, rnn_smem>>>(W_hh, b_hh, out);
}

// round 13
// speedup vs baseline: 2.1115x; 1.1387x over previous
#include <cuda_runtime.h>
#include <cuda_fp16.h>
#include <stdint.h>
#include <math.h>

#define B_  1024
#define M_  65536
#define D_  384
#define H_  384
#define K_  5

// ---- main kernel tiling ----
#define CH_   16
#define MCH   (M_/CH_)      // 4096
#define BQ    64
#define BN    128
#define BK    64
#define NT_   (MCH/BN)      // 32
#define NC_   (CH_*K_)      // 80 candidates per query

// smem (k_main): Q hi 64*768=49152, then B hi double-buffered
#define SM_B   49152
#define BSTG   16384
#define SM_TOT 81920

// ---- k_gemm2 (MMA epilogue GEMM) ----
#define G2_XT  96                    // xproj row tiles (6144/64)
#define G2_RX  112                   // + 16 gate row tiles (1024/64)
// smem: A_hi 8K | A_lo 8K | W_hi 16K | W_lo 16K
#define G2_ALO 8192
#define G2_WHI 16384
#define G2_WLO 32768
#define G2_SM  49152

#define RNS 36

// ---------------- ptx macros ----------------
#define CP_ASYNC16(dst, src) \
    asm volatile("cp.async.ca.shared.global [%0], [%1], 16;" :: "r"(dst), "l"(src))
#define CP_COMMIT() asm volatile("cp.async.commit_group;" ::: "memory")
#define CP_WAIT1()  asm volatile("cp.async.wait_group 1;" ::: "memory")
#define CP_WAIT0()  asm volatile("cp.async.wait_group 0;" ::: "memory")
#define LDM4(r0, r1, r2, r3, addr) \
    asm volatile("ldmatrix.sync.aligned.m8n8.x4.shared.b16 {%0,%1,%2,%3}, [%4];" \
                 : "=r"(r0), "=r"(r1), "=r"(r2), "=r"(r3) : "r"(addr))
#define MMA16816(c0, c1, c2, c3, a0, a1, a2, a3, b0, b1) \
    asm volatile("mma.sync.aligned.m16n8k16.row.col.f32.f16.f16.f32 " \
                 "{%0,%1,%2,%3}, {%4,%5,%6,%7}, {%8,%9}, {%0,%1,%2,%3};" \
                 : "+f"(c0), "+f"(c1), "+f"(c2), "+f"(c3) \
                 : "r"(a0), "r"(a1), "r"(a2), "r"(a3), "r"(b0), "r"(b1))

// ---------------- scratch (device globals; no allocation) ----------------
__device__ float  g_center[2];
__device__ float2 g_ra[M_];
__device__ float  g_rq[B_];
__device__ float  g_candv[B_ * NC_];
__device__ int    g_candi[B_ * NC_];
__device__ int    g_topk[B_ * K_];
__device__ float  g_xproj[B_ * 6 * H_];
__device__ float  g_gate[B_ * H_];
__device__ __half g_mem_hi[M_ * D_];
__device__ __half g_q_hi[B_ * D_];

// ---------------- kernel 1: center ----------------
__global__ void k_center(const float* __restrict__ sw) {
    __shared__ float s0[128], s1[128];
    int i = threadIdx.x;
    float a = 0.f, b = 0.f;
    for (int j = i; j < H_; j += 128) { a += sw[j * 2]; b += sw[j * 2 + 1]; }
    s0[i] = a; s1[i] = b;
    __syncthreads();
    for (int off = 64; off > 0; off >>= 1) {
        if (i < off) { s0[i] += s0[i + off]; s1[i] += s1[i + off]; }
        __syncthreads();
    }
    if (i == 0) { g_center[0] = s0[0] / (float)H_; g_center[1] = s1[0] / (float)H_; }
}

// ---------------- kernel 2: fused split + per-row stats ----------------
__global__ void k_prep(const float* __restrict__ query,
                       const float* __restrict__ mem,
                       const float* __restrict__ coords) {
    int w = (blockIdx.x * blockDim.x + threadIdx.x) >> 5;
    int lane = threadIdx.x & 31;
    if (w < M_) {
        const float2* row = (const float2*)(mem + (size_t)w * D_);
        __half2* dst = (__half2*)(g_mem_hi + (size_t)w * D_);
        float ss = 0.f;
        #pragma unroll
        for (int j = 0; j < 6; j++) {
            float2 v = row[lane + j * 32];
            ss = fmaf(v.x, v.x, fmaf(v.y, v.y, ss));
            dst[lane + j * 32] = __floats2half2_rn(v.x, v.y);
        }
        #pragma unroll
        for (int o = 16; o; o >>= 1) ss += __shfl_xor_sync(0xffffffffu, ss, o);
        if (lane == 0) {
            float dx = coords[2 * w]     - g_center[0];
            float dy = coords[2 * w + 1] - g_center[1];
            float2 ra;
            ra.x = 1.f / sqrtf(ss);
            ra.y = 1.f / (1.f + sqrtf(dx * dx + dy * dy));
            g_ra[w] = ra;
        }
    } else if (w < M_ + B_) {
        int b = w - M_;
        const float2* row = (const float2*)(query + (size_t)b * D_);
        __half2* dst = (__half2*)(g_q_hi + (size_t)b * D_);
        float ss = 0.f;
        #pragma unroll
        for (int j = 0; j < 6; j++) {
            float2 v = row[lane + j * 32];
            ss = fmaf(v.x, v.x, fmaf(v.y, v.y, ss));
            dst[lane + j * 32] = __floats2half2_rn(v.x, v.y);
        }
        #pragma unroll
        for (int o = 16; o; o >>= 1) ss += __shfl_xor_sync(0xffffffffu, ss, o);
        if (lane == 0) g_rq[b] = 1.f / sqrtf(ss);
    }
}

// ---------------- kernel 3: hi-only tensor GEMM + approx top-5 ----------------
__global__ void __launch_bounds__(256, 2) k_main() {
    extern __shared__ char smbuf[];
    uint32_t sbase;
    {
        uint64_t tmp = __cvta_generic_to_shared(smbuf);
        sbase = (uint32_t)tmp;
    }

    int tid = threadIdx.x;
    int lane = tid & 31;
    int wid = tid >> 5;
    int wq = (wid >> 2) * 32;
    int wm = (wid & 3) * 32;
    int qb = blockIdx.y * BQ;
    int mg0 = blockIdx.x * MCH;

    for (int i = tid; i < BQ * 48; i += 256) {
        int r = i / 48;
        int c = i - r * 48;
        int cs = (c & ~7) | ((c ^ r) & 7);
        *(uint4*)(smbuf + r * 768 + cs * 16) = ((const uint4*)(g_q_hi + (qb + r) * D_))[c];
    }

    float rq[4];
    #pragma unroll
    for (int l = 0; l < 4; l++)
        rq[l] = g_rq[qb + wq + (l >> 1) * 16 + (l & 1) * 8 + (lane >> 2)];

    float tv[4][K_];
    int   tix[4][K_];
    #pragma unroll
    for (int l = 0; l < 4; l++) {
        #pragma unroll
        for (int s = 0; s < K_; s++) { tv[l][s] = -3.4e38f; tix[l][s] = 0; }
    }

    __syncthreads();

    {
        const __half* bh_g = g_mem_hi + (size_t)mg0 * D_;
        uint32_t dst = sbase + SM_B;
        #pragma unroll
        for (int l = 0; l < 4; l++) {
            int i = tid + l * 256;
            int r = i >> 3;
            int seg = i & 7;
            uint32_t doff = (uint32_t)(r * 128 + (((seg ^ r) & 7) << 4));
            CP_ASYNC16(dst + doff, (const void*)(bh_g + (size_t)r * D_ + seg * 8));
        }
        CP_COMMIT();
    }

    for (int t = 0; t < NT_; t++) {
        int mg = mg0 + t * BN;

        float acc[2][4][4];
        #pragma unroll
        for (int a = 0; a < 2; a++) {
            #pragma unroll
            for (int b = 0; b < 4; b++) {
                #pragma unroll
                for (int c = 0; c < 4; c++) acc[a][b][c] = 0.f;
            }
        }

        #pragma unroll
        for (int s = 0; s < 6; s++) {
            bool issue = (s < 5) || (t + 1 < NT_);
            if (issue) {
                int kc, mnext;
                uint32_t dst;
                if (s < 5) { kc = (s + 1) * BK; mnext = mg; dst = sbase + SM_B + (uint32_t)(((s + 1) & 1) * BSTG); }
                else       { kc = 0; mnext = mg + BN; dst = sbase + SM_B; }
                const __half* bh_g = g_mem_hi + (size_t)mnext * D_;
                #pragma unroll
                for (int l = 0; l < 4; l++) {
                    int i = tid + l * 256;
                    int r = i >> 3;
                    int seg = i & 7;
                    uint32_t doff = (uint32_t)(r * 128 + (((seg ^ r) & 7) << 4));
                    CP_ASYNC16(dst + doff, (const void*)(bh_g + (size_t)r * D_ + kc + seg * 8));
                }
                CP_COMMIT();
                CP_WAIT1();
            } else {
                CP_WAIT0();
            }
            __syncthreads();

            uint32_t bbuf = sbase + SM_B + (uint32_t)((s & 1) * BSTG);
            #pragma unroll
            for (int ks = 0; ks < 4; ks++) {
                int c16 = s * 8 + ks * 2 + (lane >> 4);
                uint32_t ah[2][4];
                #pragma unroll
                for (int mt = 0; mt < 2; mt++) {
                    int qrow = wq + mt * 16 + (lane & 15);
                    int cs = (c16 & ~7) | ((c16 ^ qrow) & 7);
                    uint32_t aoff = (uint32_t)(qrow * 768 + cs * 16);
                    LDM4(ah[mt][0], ah[mt][1], ah[mt][2], ah[mt][3], sbase + aoff);
                }
                uint32_t bhf[4][2];
                #pragma unroll
                for (int p = 0; p < 2; p++) {
                    int n = wm + p * 16 + ((lane >> 4) << 3) + (lane & 7);
                    int cb = ks * 2 + ((lane >> 3) & 1);
                    uint32_t boff = (uint32_t)(n * 128 + (((cb ^ n) & 7) << 4));
                    uint32_t r0, r1, r2, r3;
                    LDM4(r0, r1, r2, r3, bbuf + boff);
                    bhf[2 * p][0] = r0; bhf[2 * p][1] = r1;
                    bhf[2 * p + 1][0] = r2; bhf[2 * p + 1][1] = r3;
                }
                #pragma unroll
                for (int mt = 0; mt < 2; mt++) {
                    #pragma unroll
                    for (int nt = 0; nt < 4; nt++) {
                        MMA16816(acc[mt][nt][0], acc[mt][nt][1], acc[mt][nt][2], acc[mt][nt][3],
                                 ah[mt][0], ah[mt][1], ah[mt][2], ah[mt][3],
                                 bhf[nt][0], bhf[nt][1]);
                    }
                }
            }
            __syncthreads();
        }

        #pragma unroll
        for (int mt = 0; mt < 2; mt++) {
            #pragma unroll
            for (int nt = 0; nt < 4; nt++) {
                int m0 = mg + wm + nt * 8 + 2 * (lane & 3);
                float4 rr4 = *(const float4*)(&g_ra[m0]);
                #pragma unroll
                for (int c = 0; c < 4; c++) {
                    int lst = mt * 2 + (c >> 1);
                    float rm  = (c & 1) ? rr4.z : rr4.x;
                    float act = (c & 1) ? rr4.w : rr4.y;
                    float v = fmaf(acc[mt][nt][c], fminf(rq[lst] * rm, 1e8f), act);
                    if (v > tv[lst][K_ - 1]) {
                        float cv = v;
                        int ci = m0 + (c & 1);
                        #pragma unroll
                        for (int s = 0; s < K_; s++) {
                            bool gt = cv > tv[lst][s];
                            float ov = tv[lst][s]; int oi = tix[lst][s];
                            tv[lst][s]  = gt ? cv : ov;
                            tix[lst][s] = gt ? ci : oi;
                            cv = gt ? ov : cv;
                            ci = gt ? oi : ci;
                        }
                    }
                }
            }
        }
    }

    __syncthreads();
    float* mv = (float*)smbuf;
    int*   mi = (int*)(smbuf + 20480);
    int slot = (wid & 3) * 4 + (lane & 3);
    #pragma unroll
    for (int l = 0; l < 4; l++) {
        int q = wq + (l >> 1) * 16 + (l & 1) * 8 + (lane >> 2);
        #pragma unroll
        for (int s = 0; s < K_; s++) {
            mv[(q * 16 + slot) * K_ + s] = tv[l][s];
            mi[(q * 16 + slot) * K_ + s] = tix[l][s];
        }
    }
    __syncthreads();
    if (tid < BQ) {
        float bv[K_];
        int bi[K_];
        #pragma unroll
        for (int s = 0; s < K_; s++) { bv[s] = -3.4e38f; bi[s] = 0; }
        #pragma unroll 4
        for (int c = 0; c < 16 * K_; c++) {
            float v = mv[tid * 80 + c];
            int  ix = mi[tid * 80 + c];
            if (v > bv[K_ - 1]) {
                float cv = v;
                int ci = ix;
                #pragma unroll
                for (int s = 0; s < K_; s++) {
                    bool gt = cv > bv[s];
                    float ov = bv[s]; int oi = bi[s];
                    bv[s] = gt ? cv : ov;
                    bi[s] = gt ? ci : oi;
                    cv = gt ? ov : cv;
                    ci = gt ? oi : ci;
                }
            }
        }
        int b = qb + tid;
        #pragma unroll
        for (int s = 0; s < K_; s++) {
            g_candv[b * NC_ + blockIdx.x * K_ + s] = bv[s];
            g_candi[b * NC_ + blockIdx.x * K_ + s] = bi[s];
        }
    }
}

// ---------------- kernel 4a: exact rescore, 8 warps per query ----------------
__global__ void __launch_bounds__(256) k_rescore1(const float* __restrict__ query,
                                                  const float* __restrict__ mem) {
    int gw = (blockIdx.x * blockDim.x + threadIdx.x) >> 5;
    int lane = threadIdx.x & 31;
    if (gw >= B_ * 8) return;
    int b = gw >> 3;
    int part = gw & 7;

    float qv[12];
    #pragma unroll
    for (int j = 0; j < 12; j++) qv[j] = query[(size_t)b * D_ + lane + j * 32];
    float rq = g_rq[b];

    #pragma unroll
    for (int c = part * 10; c < part * 10 + 10; c++) {
        int idx = g_candi[b * NC_ + c];
        const float* mrow = mem + (size_t)idx * D_;
        float dot = 0.f;
        #pragma unroll
        for (int j = 0; j < 12; j++) dot = fmaf(qv[j], mrow[lane + j * 32], dot);
        #pragma unroll
        for (int o = 16; o; o >>= 1) dot += __shfl_xor_sync(0xffffffffu, dot, o);
        if (lane == 0) {
            float2 ra = g_ra[idx];
            g_candv[b * NC_ + c] = fmaf(dot, fminf(rq * ra.x, 1e8f), ra.y);
        }
    }
}

// ---------------- kernel 4b: top-5 over exact candidates ----------------
__global__ void k_rescore2() {
    int b = blockIdx.x * blockDim.x + threadIdx.x;
    if (b >= B_) return;
    float bv[K_];
    int bi[K_];
    #pragma unroll
    for (int s = 0; s < K_; s++) { bv[s] = -3.4e38f; bi[s] = 0; }
    for (int c = 0; c < NC_; c++) {
        float v = g_candv[b * NC_ + c];
        int ix = g_candi[b * NC_ + c];
        if (v > bv[K_ - 1]) {
            float cv = v;
            int ci = ix;
            #pragma unroll
            for (int s = 0; s < K_; s++) {
                bool gt = cv > bv[s];
                float ov = bv[s]; int oi = bi[s];
                bv[s] = gt ? cv : ov;
                bi[s] = gt ? ci : oi;
                cv = gt ? ov : cv;
                ci = gt ? oi : ci;
            }
        }
    }
    #pragma unroll
    for (int s = 0; s < K_; s++) g_topk[b * K_ + s] = bi[s];
}

// ---------------- kernel 5: MMA hi/lo GEMM (xproj + gate) ----------------
// grid (112, 3): bx<96 -> xproj rows [bx*64, +64); else gate rows [(bx-96)*64, +64)
__global__ void __launch_bounds__(256, 2)
k_gemm2(const float* __restrict__ W_ih, const float* __restrict__ b_ih,
        const float* __restrict__ W_g, const float* __restrict__ b_g,
        const float* __restrict__ query, const float* __restrict__ mem) {
    extern __shared__ char smg[];
    uint32_t sbase;
    {
        uint64_t tmp = __cvta_generic_to_shared(smg);
        sbase = (uint32_t)tmp;
    }
    int tid = threadIdx.x;
    int lane = tid & 31;
    int wid = tid >> 5;
    int wq = (wid & 1) * 32;        // row group (64 rows / 2)
    int wn = (wid >> 1) * 32;       // col group (128 cols / 4)

    int bx = blockIdx.x;
    int mode = (bx < G2_XT) ? 0 : 1;
    int rb = (mode == 0) ? bx * 64 : (bx - G2_XT) * 64;
    int hb = blockIdx.y * 128;
    const float* W = (mode == 0) ? W_ih : W_g;
    const float* bias = (mode == 0) ? b_ih : b_g;

    float acc[2][4][4];
    #pragma unroll
    for (int a = 0; a < 2; a++) {
        #pragma unroll
        for (int b = 0; b < 4; b++) {
            #pragma unroll
            for (int c = 0; c < 4; c++) acc[a][b][c] = 0.f;
        }
    }

    for (int s = 0; s < 6; s++) {
        int kc = s * 64;
        __syncthreads();
        // A tile: 64 rows x 64 k -> hi/lo fp16, swizzled (2 chunks/thread)
        #pragma unroll
        for (int l = 0; l < 2; l++) {
            int i = tid + l * 256;
            int r = i >> 3;
            int seg = i & 7;
            int rg = rb + r;
            const float* src;
            if (mode == 0) {
                int bq = rg / 6;
                int tt = rg - bq * 6;
                if (tt == 0) src = query + (size_t)bq * D_;
                else src = mem + (size_t)g_topk[bq * K_ + tt - 1] * D_;
            } else {
                src = query + (size_t)rg * D_;
            }
            float4 v1 = *(const float4*)(src + kc + seg * 8);
            float4 v2 = *(const float4*)(src + kc + seg * 8 + 4);
            float xs[8];
            xs[0] = v1.x; xs[1] = v1.y; xs[2] = v1.z; xs[3] = v1.w;
            xs[4] = v2.x; xs[5] = v2.y; xs[6] = v2.z; xs[7] = v2.w;
            uint32_t hw[8], lw[8];
            #pragma unroll
            for (int k = 0; k < 8; k++) {
                __half hb2 = __float2half_rn(xs[k]);
                hw[k] = (uint32_t)__half_as_ushort(hb2);
                lw[k] = (uint32_t)__half_as_ushort(__float2half_rn(xs[k] - __half2float(hb2)));
            }
            uint4 hv, lv;
            hv.x = hw[0] | (hw[1] << 16); hv.y = hw[2] | (hw[3] << 16);
            hv.z = hw[4] | (hw[5] << 16); hv.w = hw[6] | (hw[7] << 16);
            lv.x = lw[0] | (lw[1] << 16); lv.y = lw[2] | (lw[3] << 16);
            lv.z = lw[4] | (lw[5] << 16); lv.w = lw[6] | (lw[7] << 16);
            uint32_t doff = (uint32_t)(r * 128 + (((seg ^ r) & 7) << 4));
            *(uint4*)(smg + doff) = hv;
            *(uint4*)(smg + G2_ALO + doff) = lv;
        }
        // W tile: 128 rows x 64 k -> hi/lo, swizzled (4 chunks/thread)
        #pragma unroll
        for (int l = 0; l < 4; l++) {
            int i = tid + l * 256;
            int h = i >> 3;
            int seg = i & 7;
            const float* src = W + (size_t)(hb + h) * D_ + kc + seg * 8;
            float4 v1 = *(const float4*)(src);
            float4 v2 = *(const float4*)(src + 4);
            float xs[8];
            xs[0] = v1.x; xs[1] = v1.y; xs[2] = v1.z; xs[3] = v1.w;
            xs[4] = v2.x; xs[5] = v2.y; xs[6] = v2.z; xs[7] = v2.w;
            uint32_t hw[8], lw[8];
            #pragma unroll
            for (int k = 0; k < 8; k++) {
                __half hb2 = __float2half_rn(xs[k]);
                hw[k] = (uint32_t)__half_as_ushort(hb2);
                lw[k] = (uint32_t)__half_as_ushort(__float2half_rn(xs[k] - __half2float(hb2)));
            }
            uint4 hv, lv;
            hv.x = hw[0] | (hw[1] << 16); hv.y = hw[2] | (hw[3] << 16);
            hv.z = hw[4] | (hw[5] << 16); hv.w = hw[6] | (hw[7] << 16);
            lv.x = lw[0] | (lw[1] << 16); lv.y = lw[2] | (lw[3] << 16);
            lv.z = lw[4] | (lw[5] << 16); lv.w = lw[6] | (lw[7] << 16);
            uint32_t doff = (uint32_t)(h * 128 + (((seg ^ h) & 7) << 4));
            *(uint4*)(smg + G2_WHI + doff) = hv;
            *(uint4*)(smg + G2_WLO + doff) = lv;
        }
        __syncthreads();

        #pragma unroll
        for (int ks = 0; ks < 4; ks++) {
            uint32_t ah[2][4], al[2][4];
            #pragma unroll
            for (int mt = 0; mt < 2; mt++) {
                int qrow = wq + mt * 16 + (lane & 15);
                int c16 = ks * 2 + (lane >> 4);
                int cs = (c16 ^ qrow) & 7;
                uint32_t aoff = (uint32_t)(qrow * 128 + cs * 16);
                LDM4(ah[mt][0], ah[mt][1], ah[mt][2], ah[mt][3], sbase + aoff);
                LDM4(al[mt][0], al[mt][1], al[mt][2], al[mt][3], sbase + G2_ALO + aoff);
            }
            uint32_t bh[4][2], bl[4][2];
            #pragma unroll
            for (int p = 0; p < 2; p++) {
                int n = wn + p * 16 + ((lane >> 4) << 3) + (lane & 7);
                int cb = ks * 2 + ((lane >> 3) & 1);
                uint32_t boff = (uint32_t)(n * 128 + (((cb ^ n) & 7) << 4));
                uint32_t r0, r1, r2, r3;
                LDM4(r0, r1, r2, r3, sbase + G2_WHI + boff);
                bh[2 * p][0] = r0; bh[2 * p][1] = r1;
                bh[2 * p + 1][0] = r2; bh[2 * p + 1][1] = r3;
                LDM4(r0, r1, r2, r3, sbase + G2_WLO + boff);
                bl[2 * p][0] = r0; bl[2 * p][1] = r1;
                bl[2 * p + 1][0] = r2; bl[2 * p + 1][1] = r3;
            }
            #pragma unroll
            for (int mt = 0; mt < 2; mt++) {
                #pragma unroll
                for (int nt = 0; nt < 4; nt++) {
                    MMA16816(acc[mt][nt][0], acc[mt][nt][1], acc[mt][nt][2], acc[mt][nt][3],
                             ah[mt][0], ah[mt][1], ah[mt][2], ah[mt][3],
                             bh[nt][0], bh[nt][1]);
                }
            }
            #pragma unroll
            for (int mt = 0; mt < 2; mt++) {
                #pragma unroll
                for (int nt = 0; nt < 4; nt++) {
                    MMA16816(acc[mt][nt][0], acc[mt][nt][1], acc[mt][nt][2], acc[mt][nt][3],
                             al[mt][0], al[mt][1], al[mt][2], al[mt][3],
                             bh[nt][0], bh[nt][1]);
                }
            }
            #pragma unroll
            for (int mt = 0; mt < 2; mt++) {
                #pragma unroll
                for (int nt = 0; nt < 4; nt++) {
                    MMA16816(acc[mt][nt][0], acc[mt][nt][1], acc[mt][nt][2], acc[mt][nt][3],
                             ah[mt][0], ah[mt][1], ah[mt][2], ah[mt][3],
                             bl[nt][0], bl[nt][1]);
                }
            }
        }
    }

    float* out = (mode == 0) ? g_xproj : g_gate;
    #pragma unroll
    for (int mt = 0; mt < 2; mt++) {
        #pragma unroll
        for (int nt = 0; nt < 4; nt++) {
            int r0o = rb + wq + mt * 16 + (lane >> 2);
            int h0 = hb + wn + nt * 8 + 2 * (lane & 3);
            #pragma unroll
            for (int c = 0; c < 4; c++) {
                int rr = r0o + (c >> 1) * 8;
                int hh = h0 + (c & 1);
                float v = acc[mt][nt][c] + bias[hh];
                if (mode == 1) v = 1.f / (1.f + expf(-v));
                out[rr * H_ + hh] = v;
            }
        }
    }
}

// ---------------- kernel 6: fused RNN ----------------
__global__ void __launch_bounds__(256) k_rnn(const float* __restrict__ Whh,
                                             const float* __restrict__ bhh,
                                             float* __restrict__ out) {
    extern __shared__ float rs[];
    float* h_s = rs;
    float* w_s = rs + 8 * H_;
    int tid = threadIdx.x;
    int r0 = blockIdx.x * 8;

    int rr[12], hh[12];
    #pragma unroll
    for (int o = 0; o < 12; o++) {
        int idx = o * 256 + tid;
        rr[o] = idx / H_;
        hh[o] = idx - rr[o] * H_;
    }

    #pragma unroll
    for (int o = 0; o < 12; o++)
        h_s[rr[o] * H_ + hh[o]] = tanhf(g_xproj[(r0 + rr[o]) * (6 * H_) + hh[o]] + bhh[hh[o]]);
    __syncthreads();

    for (int t = 1; t <= 5; t++) {
        float hn[12];
        #pragma unroll
        for (int o = 0; o < 12; o++)
            hn[o] = g_xproj[(r0 + rr[o]) * (6 * H_) + t * H_ + hh[o]] + bhh[hh[o]];

        for (int k0 = 0; k0 < H_; k0 += 32) {
            __syncthreads();
            for (int i = tid; i < 32 * H_; i += 256) {
                int kk = i & 31;
                int h = i >> 5;
                w_s[h * RNS + kk] = Whh[h * H_ + k0 + kk];
            }
            __syncthreads();
            #pragma unroll
            for (int o = 0; o < 12; o++) {
                const float4* wp = (const float4*)(w_s + hh[o] * RNS);
                const float4* hp = (const float4*)(h_s + rr[o] * H_ + k0);
                float a = 0.f;
                #pragma unroll
                for (int k4 = 0; k4 < 8; k4++) {
                    float4 w4 = wp[k4];
                    float4 h4 = hp[k4];
                    a = fmaf(w4.x, h4.x, a);
                    a = fmaf(w4.y, h4.y, a);
                    a = fmaf(w4.z, h4.z, a);
                    a = fmaf(w4.w, h4.w, a);
                }
                hn[o] += a;
            }
        }
        __syncthreads();
        if (t < 5) {
            #pragma unroll
            for (int o = 0; o < 12; o++) h_s[rr[o] * H_ + hh[o]] = tanhf(hn[o]);
            __syncthreads();
        } else {
            #pragma unroll
            for (int o = 0; o < 12; o++) {
                int gi = (r0 + rr[o]) * H_ + hh[o];
                float g = g_gate[gi];
                float direct = g_xproj[(r0 + rr[o]) * (6 * H_) + hh[o]];
                out[gi] = g * tanhf(hn[o]) + (1.f - g) * direct;
            }
        }
    }
}

// ---------------- launch ----------------
extern "C" void kernel_launch(void* const* d_in, const int* in_sizes, int n_in,
                              void* d_out, int out_size) {
    const float* query  = (const float*)d_in[0];
    const float* mem    = (const float*)d_in[1];
    const float* coords = (const float*)d_in[2];
    const float* sw     = (const float*)d_in[3];
    const float* W_ih   = (const float*)d_in[4];
    const float* b_ih   = (const float*)d_in[5];
    const float* W_hh   = (const float*)d_in[6];
    const float* b_hh   = (const float*)d_in[7];
    const float* W_g    = (const float*)d_in[8];
    const float* b_g    = (const float*)d_in[9];
    float* out = (float*)d_out;

    k_center<<<1, 128>>>(sw);
    k_prep<<<(M_ + B_) / 8, 256>>>(query, mem, coords);

    cudaFuncSetAttribute(k_main, cudaFuncAttributeMaxDynamicSharedMemorySize, SM_TOT);
    k_main<<<dim3(CH_, B_ / BQ), 256, SM_TOT>>>();

    k_rescore1<<<B_, 256>>>(query, mem);
    k_rescore2<<<4, 256>>>();

    cudaFuncSetAttribute(k_gemm2, cudaFuncAttributeMaxDynamicSharedMemorySize, G2_SM);
    k_gemm2<<<dim3(G2_RX, 3), 256, G2_SM>>>(W_ih, b_ih, W_g, b_g, query, mem);

    int rnn_smem = (8 * H_ + H_ * RNS) * 4;
    cudaFuncSetAttribute(k_rnn, cudaFuncAttributeMaxDynamicSharedMemorySize, rnn_smem);
    k_rnn<<<B_ / 8, 256, rnn_smem>>>(W_hh, b_hh, out);
}